// round 2
// baseline (speedup 1.0000x reference)
#include <cuda_runtime.h>
#include <math.h>

// ---------------- static scratch (no allocation allowed) ----------------
#define MAXN 100096
#define MAXE 1600512
#define SCAN_B 1024

__device__ int   g_indeg[MAXN];
__device__ int   g_cursor[MAXN];
__device__ int   g_rowptr[MAXN + 1];
__device__ int   g_bsum[1024];
__device__ float g_dinv[MAXN];
__device__ int   g_csrc[MAXE];
__device__ float g_xw[MAXN * 128];   // linear output buffer
__device__ float g_h[MAXN * 128];    // activation buffer (input to next layer)

// ---------------- setup kernels ----------------
__global__ void init_k(int n) {
    int i = blockIdx.x * blockDim.x + threadIdx.x;
    if (i < n) { g_indeg[i] = 0; g_cursor[i] = 0; }
}

// edge_index is int32 (JAX x64 disabled downcasts int64 -> int32)
__global__ void hist_k(const int* __restrict__ ei, int e) {
    int i = blockIdx.x * blockDim.x + threadIdx.x;
    if (i < e) atomicAdd(&g_indeg[ei[e + i]], 1);   // dst row
}

__global__ void dinv_k(int n) {
    int i = blockIdx.x * blockDim.x + threadIdx.x;
    if (i < n) g_dinv[i] = rsqrtf((float)(g_indeg[i] + 1));  // +1 self-loop
}

// exclusive block scan of indeg -> rowptr (partial), block sums -> g_bsum
__global__ void scan_blocks_k(int n) {
    __shared__ int sh[SCAN_B];
    int i = blockIdx.x * SCAN_B + threadIdx.x;
    int v = (i < n) ? g_indeg[i] : 0;
    sh[threadIdx.x] = v;
    __syncthreads();
    for (int off = 1; off < SCAN_B; off <<= 1) {
        int t = (threadIdx.x >= off) ? sh[threadIdx.x - off] : 0;
        __syncthreads();
        sh[threadIdx.x] += t;
        __syncthreads();
    }
    int incl = sh[threadIdx.x];
    if (i < n) g_rowptr[i] = incl - v;     // exclusive
    if (threadIdx.x == SCAN_B - 1) g_bsum[blockIdx.x] = incl;
}

__global__ void scan_bsums_k(int nb) {
    if (threadIdx.x == 0 && blockIdx.x == 0) {
        int acc = 0;
        for (int i = 0; i < nb; i++) { int v = g_bsum[i]; g_bsum[i] = acc; acc += v; }
    }
}

__global__ void add_offsets_k(int n, int e) {
    int i = blockIdx.x * SCAN_B + threadIdx.x;
    if (i < n) g_rowptr[i] += g_bsum[blockIdx.x];
    if (i == 0) g_rowptr[n] = e;
}

__global__ void scatter_k(const int* __restrict__ ei, int e) {
    int i = blockIdx.x * blockDim.x + threadIdx.x;
    if (i >= e) return;
    int s = ei[i];
    int d = ei[e + i];
    int pos = g_rowptr[d] + atomicAdd(&g_cursor[d], 1);
    g_csrc[pos] = s;
}

// ---------------- GEMM: out[n, DOUT] = h[n, DIN] @ W[DIN, DOUT] ----------------
template <int DIN, int DOUT>
__global__ void gemm_k(const float* __restrict__ h, const float* __restrict__ W,
                       float* __restrict__ out, int n) {
    constexpr int RPB = 256 / DOUT;           // rows per block
    __shared__ float Ws[DIN * DOUT];
    __shared__ float Hs[RPB][DIN];
    for (int i = threadIdx.x; i < DIN * DOUT; i += 256) Ws[i] = W[i];
    for (int i = threadIdx.x; i < RPB * DIN; i += 256) {
        int rr = i / DIN, kk = i % DIN;
        int grow = blockIdx.x * RPB + rr;
        Hs[rr][kk] = (grow < n) ? h[grow * DIN + kk] : 0.f;
    }
    __syncthreads();
    int f = threadIdx.x % DOUT;
    int r = threadIdx.x / DOUT;
    int row = blockIdx.x * RPB + r;
    float acc = 0.f;
#pragma unroll
    for (int k = 0; k < DIN; k++) acc += Hs[r][k] * Ws[k * DOUT + f];
    if (row < n) out[row * DOUT + f] = acc;
}

// layer 4 GEMM: din=128 -> dout=1, warp per row
__global__ void gemm4_k(const float* __restrict__ h, const float* __restrict__ W,
                        float* __restrict__ out, int n) {
    int warp = (blockIdx.x * blockDim.x + threadIdx.x) >> 5;
    int lane = threadIdx.x & 31;
    if (warp >= n) return;
    float acc = 0.f;
#pragma unroll
    for (int k = lane; k < 128; k += 32) acc += h[warp * 128 + k] * __ldg(&W[k]);
#pragma unroll
    for (int off = 16; off; off >>= 1) acc += __shfl_down_sync(0xffffffffu, acc, off);
    if (lane == 0) out[warp] = acc;
}

// ---------------- aggregation + bias + BN(eval) + ELU ----------------
template <int DOUT>
__global__ void agg_k(const float* __restrict__ xw,
                      const float* __restrict__ b, const float* __restrict__ g,
                      const float* __restrict__ be, const float* __restrict__ rm,
                      const float* __restrict__ rv, float* __restrict__ out, int n) {
    constexpr int NPB = 256 / DOUT;
    int f = threadIdx.x % DOUT;
    int yr = threadIdx.x / DOUT;
    int node = blockIdx.x * NPB + yr;
    if (node >= n) return;
    float di = g_dinv[node];
    float acc = xw[node * DOUT + f] * di * di;        // self-loop
    int e0 = g_rowptr[node], e1 = g_rowptr[node + 1];
    for (int e = e0; e < e1; e++) {
        int s = g_csrc[e];
        float w = g_dinv[s] * di;
        acc += xw[s * DOUT + f] * w;
    }
    float v = acc + b[f];
    v = (v - rm[f]) * rsqrtf(rv[f] + 1e-5f) * g[f] + be[f];
    v = (v > 0.f) ? v : expm1f(v);
    out[node * DOUT + f] = v;
}

// last layer: dout=1, thread per node; +bias, ELU, sigmoid
__global__ void agg_last_k(const float* __restrict__ xw, const float* __restrict__ b,
                           float* __restrict__ out, int n) {
    int node = blockIdx.x * blockDim.x + threadIdx.x;
    if (node >= n) return;
    float di = g_dinv[node];
    float acc = xw[node] * di * di;
    int e0 = g_rowptr[node], e1 = g_rowptr[node + 1];
    for (int e = e0; e < e1; e++) {
        int s = g_csrc[e];
        acc += xw[s] * g_dinv[s] * di;
    }
    float v = acc + b[0];
    v = (v > 0.f) ? v : expm1f(v);
    out[node] = 1.f / (1.f + expf(-v));
}

// ---------------- launch ----------------
extern "C" void kernel_launch(void* const* d_in, const int* in_sizes, int n_in,
                              void* d_out, int out_size) {
    const float* x  = (const float*)d_in[0];
    const int*   ei = (const int*)d_in[1];
    const float* W1 = (const float*)d_in[2];  const float* b1 = (const float*)d_in[3];
    const float* W2 = (const float*)d_in[4];  const float* b2 = (const float*)d_in[5];
    const float* W3 = (const float*)d_in[6];  const float* b3 = (const float*)d_in[7];
    const float* W4 = (const float*)d_in[8];  const float* b4 = (const float*)d_in[9];
    const float* g1 = (const float*)d_in[10]; const float* be1 = (const float*)d_in[11];
    const float* rm1 = (const float*)d_in[12]; const float* rv1 = (const float*)d_in[13];
    const float* g2 = (const float*)d_in[14]; const float* be2 = (const float*)d_in[15];
    const float* rm2 = (const float*)d_in[16]; const float* rv2 = (const float*)d_in[17];
    const float* g3 = (const float*)d_in[18]; const float* be3 = (const float*)d_in[19];
    const float* rm3 = (const float*)d_in[20]; const float* rv3 = (const float*)d_in[21];

    int n = in_sizes[0] / 64;       // 100000
    int e = in_sizes[1] / 2;        // 1600000

    float* xw; cudaGetSymbolAddress((void**)&xw, g_xw);
    float* h;  cudaGetSymbolAddress((void**)&h,  g_h);
    float* out = (float*)d_out;

    int nb_n  = (n + 255) / 256;
    int nb_e  = (e + 255) / 256;
    int nb_sc = (n + SCAN_B - 1) / SCAN_B;

    // --- build CSR + normalization ---
    init_k<<<nb_n, 256>>>(n);
    hist_k<<<nb_e, 256>>>(ei, e);
    dinv_k<<<nb_n, 256>>>(n);
    scan_blocks_k<<<nb_sc, SCAN_B>>>(n);
    scan_bsums_k<<<1, 32>>>(nb_sc);
    add_offsets_k<<<nb_sc, SCAN_B>>>(n, e);
    scatter_k<<<nb_e, 256>>>(ei, e);

    // --- layer 1: 64 -> 32 ---
    gemm_k<64, 32><<<(n + 7) / 8, 256>>>(x, W1, xw, n);
    agg_k<32><<<(n + 7) / 8, 256>>>(xw, b1, g1, be1, rm1, rv1, h, n);

    // --- layer 2: 32 -> 64 ---
    gemm_k<32, 64><<<(n + 3) / 4, 256>>>(h, W2, xw, n);
    agg_k<64><<<(n + 3) / 4, 256>>>(xw, b2, g2, be2, rm2, rv2, h, n);

    // --- layer 3: 64 -> 128 ---
    gemm_k<64, 128><<<(n + 1) / 2, 256>>>(h, W3, xw, n);
    agg_k<128><<<(n + 1) / 2, 256>>>(xw, b3, g3, be3, rm3, rv3, h, n);

    // --- layer 4: 128 -> 1, + ELU + sigmoid ---
    gemm4_k<<<(n * 32 + 255) / 256, 256>>>(h, W4, xw, n);
    agg_last_k<<<nb_n, 256>>>(xw, b4, out, n);
}

// round 4
// speedup vs baseline: 1.2989x; 1.2989x over previous
#include <cuda_runtime.h>
#include <math.h>

// ---------------- static scratch (no allocation allowed) ----------------
#define MAXN 100096
#define MAXE 1600512
#define SCAN_B 1024

__device__ int   g_indeg[MAXN];
__device__ int   g_cursor[MAXN];
__device__ int   g_rowptr[MAXN + 1];
__device__ int   g_bsum[1024];
__device__ float g_dinv[MAXN];
__device__ int   g_csrc[MAXE];
__device__ float g_bufA[MAXN * 128];
__device__ float g_bufB[MAXN * 128];

__device__ __forceinline__ float4 f4add(float4 a, float4 b) {
    return make_float4(a.x + b.x, a.y + b.y, a.z + b.z, a.w + b.w);
}

// ---------------- setup kernels ----------------
__global__ void init_k(int n) {
    int i = blockIdx.x * blockDim.x + threadIdx.x;
    if (i < n) { g_indeg[i] = 0; g_cursor[i] = 0; }
}

// edge_index is int32 (JAX x64 disabled: int64 request -> int32 array)
__global__ void hist_k(const int* __restrict__ ei, int e) {
    int i = blockIdx.x * blockDim.x + threadIdx.x;
    if (i < e) atomicAdd(&g_indeg[ei[e + i]], 1);   // dst row
}

__global__ void dinv_k(int n) {
    int i = blockIdx.x * blockDim.x + threadIdx.x;
    if (i < n) g_dinv[i] = rsqrtf((float)(g_indeg[i] + 1));  // +1 self-loop
}

__global__ void scan_blocks_k(int n) {
    __shared__ int sh[SCAN_B];
    int i = blockIdx.x * SCAN_B + threadIdx.x;
    int v = (i < n) ? g_indeg[i] : 0;
    sh[threadIdx.x] = v;
    __syncthreads();
    for (int off = 1; off < SCAN_B; off <<= 1) {
        int t = (threadIdx.x >= off) ? sh[threadIdx.x - off] : 0;
        __syncthreads();
        sh[threadIdx.x] += t;
        __syncthreads();
    }
    int incl = sh[threadIdx.x];
    if (i < n) g_rowptr[i] = incl - v;     // exclusive
    if (threadIdx.x == SCAN_B - 1) g_bsum[blockIdx.x] = incl;
}

__global__ void scan_bsums_k(int nb) {
    if (threadIdx.x == 0 && blockIdx.x == 0) {
        int acc = 0;
        for (int i = 0; i < nb; i++) { int v = g_bsum[i]; g_bsum[i] = acc; acc += v; }
    }
}

__global__ void add_offsets_k(int n, int e) {
    int i = blockIdx.x * SCAN_B + threadIdx.x;
    if (i < n) g_rowptr[i] += g_bsum[blockIdx.x];
    if (i == 0) g_rowptr[n] = e;
}

__global__ void scatter_k(const int* __restrict__ ei, int e) {
    int i = blockIdx.x * blockDim.x + threadIdx.x;
    if (i >= e) return;
    int s = ei[i];
    int d = ei[e + i];
    int pos = g_rowptr[d] + atomicAdd(&g_cursor[d], 1);
    g_csrc[pos] = s;
}

// ---------------- GEMM variants ----------------
// EPI: 0 = out = acc * dinv[row]                     (L1: pre-agg scale)
//      1 = out = ELU(BN(acc + b)) * dinv[row]        (L2: post-agg transform, store scaled)
//      2 = out = ELU(BN(acc + b))                    (L3: next layer transforms first)
template <int DIN, int DOUT, int EPI>
__global__ void gemm_k(const float* __restrict__ h, const float* __restrict__ W,
                       const float* __restrict__ b, const float* __restrict__ g,
                       const float* __restrict__ be, const float* __restrict__ rm,
                       const float* __restrict__ rv, float* __restrict__ out, int n) {
    constexpr int RPB = 256 / DOUT;
    __shared__ float Ws[DIN * DOUT];
    __shared__ float Hs[RPB][DIN];
    for (int i = threadIdx.x; i < DIN * DOUT; i += 256) Ws[i] = W[i];
    for (int i = threadIdx.x; i < RPB * DIN; i += 256) {
        int rr = i / DIN, kk = i % DIN;
        int grow = blockIdx.x * RPB + rr;
        Hs[rr][kk] = (grow < n) ? h[grow * DIN + kk] : 0.f;
    }
    __syncthreads();
    int f = threadIdx.x % DOUT;
    int r = threadIdx.x / DOUT;
    int row = blockIdx.x * RPB + r;
    float acc = 0.f;
#pragma unroll
    for (int k = 0; k < DIN; k++) acc += Hs[r][k] * Ws[k * DOUT + f];
    if (row >= n) return;
    if (EPI == 0) {
        out[row * DOUT + f] = acc * g_dinv[row];
    } else {
        float v = acc + b[f];
        v = (v - rm[f]) * rsqrtf(rv[f] + 1e-5f) * g[f] + be[f];
        v = (v > 0.f) ? v : expm1f(v);
        if (EPI == 1) v *= g_dinv[row];
        out[row * DOUT + f] = v;
    }
}

// layer 4 GEMM: din=128 -> dout=1, warp per row; output scaled by dinv[row]
__global__ void gemm4_k(const float* __restrict__ h, const float* __restrict__ W,
                        float* __restrict__ out, int n) {
    int warp = (blockIdx.x * blockDim.x + threadIdx.x) >> 5;
    int lane = threadIdx.x & 31;
    if (warp >= n) return;
    float acc = 0.f;
#pragma unroll
    for (int k = lane; k < 128; k += 32) acc += h[warp * 128 + k] * __ldg(&W[k]);
#pragma unroll
    for (int off = 16; off; off >>= 1) acc += __shfl_down_sync(0xffffffffu, acc, off);
    if (lane == 0) out[warp] = acc * g_dinv[warp];
}

// ---------------- aggregation (gather over CSR, float4 rows) ----------------
// Input rows are pre-scaled by dinv[src]. Result row = dinv[node] * (self + sum neighbors).
// W4 = row width in float4. EPI: 0 = plain; 1 = +b, BN, ELU, then *dinv (L1 output)
template <int W4, int EPI>
__global__ void agg_k(const float* __restrict__ in_,
                      const float* __restrict__ b, const float* __restrict__ g,
                      const float* __restrict__ be, const float* __restrict__ rm,
                      const float* __restrict__ rv, float* __restrict__ out_, int n) {
    constexpr int NPB = 256 / W4;
    const float4* in = (const float4*)in_;
    float4* out = (float4*)out_;
    int f4 = threadIdx.x % W4;
    int ln = threadIdx.x / W4;
    int node = blockIdx.x * NPB + ln;
    if (node >= n) return;
    float di = g_dinv[node];
    float4 a0 = in[node * W4 + f4];                 // self (already *dinv[node])
    float4 a1 = make_float4(0.f, 0.f, 0.f, 0.f);
    int e0 = g_rowptr[node], e1 = g_rowptr[node + 1];
    int e = e0;
    for (; e + 1 < e1; e += 2) {
        int s0 = g_csrc[e];
        int s1 = g_csrc[e + 1];
        float4 r0 = in[s0 * W4 + f4];
        float4 r1 = in[s1 * W4 + f4];
        a0 = f4add(a0, r0);
        a1 = f4add(a1, r1);
    }
    if (e < e1) a0 = f4add(a0, in[g_csrc[e] * W4 + f4]);
    float4 t = f4add(a0, a1);
    t.x *= di; t.y *= di; t.z *= di; t.w *= di;
    if (EPI == 1) {
        const float4* b4 = (const float4*)b;   const float4* g4 = (const float4*)g;
        const float4* be4 = (const float4*)be; const float4* rm4 = (const float4*)rm;
        const float4* rv4 = (const float4*)rv;
        float4 vb = b4[f4], vg = g4[f4], vbe = be4[f4], vrm = rm4[f4], vrv = rv4[f4];
        float4 v;
        v.x = (t.x + vb.x - vrm.x) * rsqrtf(vrv.x + 1e-5f) * vg.x + vbe.x;
        v.y = (t.y + vb.y - vrm.y) * rsqrtf(vrv.y + 1e-5f) * vg.y + vbe.y;
        v.z = (t.z + vb.z - vrm.z) * rsqrtf(vrv.z + 1e-5f) * vg.z + vbe.z;
        v.w = (t.w + vb.w - vrm.w) * rsqrtf(vrv.w + 1e-5f) * vg.w + vbe.w;
        v.x = (v.x > 0.f) ? v.x : expm1f(v.x);
        v.y = (v.y > 0.f) ? v.y : expm1f(v.y);
        v.z = (v.z > 0.f) ? v.z : expm1f(v.z);
        v.w = (v.w > 0.f) ? v.w : expm1f(v.w);
        v.x *= di; v.y *= di; v.z *= di; v.w *= di;   // pre-scale for next layer's agg
        out[node * W4 + f4] = v;
    } else {
        out[node * W4 + f4] = t;
    }
}

// last layer: dout=1; in = (h3@W4)*dinv. v = di*(self+sum)+b, ELU, sigmoid
__global__ void agg_last_k(const float* __restrict__ in, const float* __restrict__ b,
                           float* __restrict__ out, int n) {
    int node = blockIdx.x * blockDim.x + threadIdx.x;
    if (node >= n) return;
    float di = g_dinv[node];
    float a0 = in[node], a1 = 0.f;
    int e0 = g_rowptr[node], e1 = g_rowptr[node + 1];
    int e = e0;
    for (; e + 1 < e1; e += 2) {
        a0 += in[g_csrc[e]];
        a1 += in[g_csrc[e + 1]];
    }
    if (e < e1) a0 += in[g_csrc[e]];
    float v = (a0 + a1) * di + b[0];
    v = (v > 0.f) ? v : expm1f(v);
    out[node] = 1.f / (1.f + expf(-v));
}

// ---------------- launch ----------------
extern "C" void kernel_launch(void* const* d_in, const int* in_sizes, int n_in,
                              void* d_out, int out_size) {
    const float* x  = (const float*)d_in[0];
    const int*   ei = (const int*)d_in[1];
    const float* W1 = (const float*)d_in[2];  const float* b1 = (const float*)d_in[3];
    const float* W2 = (const float*)d_in[4];  const float* b2 = (const float*)d_in[5];
    const float* W3 = (const float*)d_in[6];  const float* b3 = (const float*)d_in[7];
    const float* W4 = (const float*)d_in[8];  const float* b4 = (const float*)d_in[9];
    const float* g1 = (const float*)d_in[10]; const float* be1 = (const float*)d_in[11];
    const float* rm1 = (const float*)d_in[12]; const float* rv1 = (const float*)d_in[13];
    const float* g2 = (const float*)d_in[14]; const float* be2 = (const float*)d_in[15];
    const float* rm2 = (const float*)d_in[16]; const float* rv2 = (const float*)d_in[17];
    const float* g3 = (const float*)d_in[18]; const float* be3 = (const float*)d_in[19];
    const float* rm3 = (const float*)d_in[20]; const float* rv3 = (const float*)d_in[21];

    int n = in_sizes[0] / 64;       // 100000
    int e = in_sizes[1] / 2;        // 1600000

    float* A; cudaGetSymbolAddress((void**)&A, g_bufA);
    float* B; cudaGetSymbolAddress((void**)&B, g_bufB);
    float* out = (float*)d_out;

    int nb_n  = (n + 255) / 256;
    int nb_e  = (e + 255) / 256;
    int nb_sc = (n + SCAN_B - 1) / SCAN_B;

    // --- build CSR + normalization ---
    init_k<<<nb_n, 256>>>(n);
    hist_k<<<nb_e, 256>>>(ei, e);
    dinv_k<<<nb_n, 256>>>(n);
    scan_blocks_k<<<nb_sc, SCAN_B>>>(n);
    scan_bsums_k<<<1, 32>>>(nb_sc);
    add_offsets_k<<<nb_sc, SCAN_B>>>(n, e);
    scatter_k<<<nb_e, 256>>>(ei, e);

    // --- layer 1: transform (64->32, *dinv) then agg (+BN/ELU, *dinv) ---
    gemm_k<64, 32, 0><<<(n + 7) / 8, 256>>>(x, W1, 0, 0, 0, 0, 0, A, n);
    agg_k<8, 1><<<(n + 31) / 32, 256>>>(A, b1, g1, be1, rm1, rv1, B, n);   // B = h1*dinv (w32)

    // --- layer 2: agg first (w32), then transform (32->64, +BN/ELU, *dinv) ---
    agg_k<8, 0><<<(n + 31) / 32, 256>>>(B, 0, 0, 0, 0, 0, A, n);           // A = Agg(h1) (w32)
    gemm_k<32, 64, 1><<<(n + 3) / 4, 256>>>(A, W2, b2, g2, be2, rm2, rv2, B, n);  // B = h2*dinv (w64)

    // --- layer 3: agg first (w64), then transform (64->128, +BN/ELU) ---
    agg_k<16, 0><<<(n + 15) / 16, 256>>>(B, 0, 0, 0, 0, 0, A, n);          // A = Agg(h2) (w64)
    gemm_k<64, 128, 2><<<(n + 1) / 2, 256>>>(A, W3, b3, g3, be3, rm3, rv3, B, n); // B = h3 (w128)

    // --- layer 4: transform (128->1, *dinv), agg + ELU + sigmoid ---
    gemm4_k<<<(n * 32 + 255) / 256, 256>>>(B, W4, A, n);
    agg_last_k<<<nb_n, 256>>>(A, b4, out, n);
}

// round 5
// speedup vs baseline: 1.4444x; 1.1120x over previous
#include <cuda_runtime.h>
#include <cuda_fp16.h>
#include <math.h>

#define MAXN 100096
#define MAXE 1600512
#define SCAN_B 1024
#define EPS 1e-5f

// ---------------- static scratch ----------------
__device__ int    g_indeg[MAXN];
__device__ int    g_cursor[MAXN];
__device__ int    g_rowptr[MAXN + 1];
__device__ int    g_bsum[1024];
__device__ float  g_dinv[MAXN];
__device__ int    g_csrc[MAXE];
__device__ __half g_hA[MAXN * 64];
__device__ __half g_hB[MAXN * 64];
__device__ float  g_f32[MAXN * 128];
__device__ float  g_scal[MAXN];
__device__ float  g_bnS[32];
__device__ float  g_bnT[32];

// ---------------- half helpers ----------------
__device__ __forceinline__ __half2 u2h(unsigned u) {
    __half2 h; *reinterpret_cast<unsigned*>(&h) = u; return h;
}
__device__ __forceinline__ unsigned h2u(__half2 h) {
    return *reinterpret_cast<unsigned*>(&h);
}
__device__ __forceinline__ void cvt8(uint4 v, float* f) {
    float2 a = __half22float2(u2h(v.x));
    float2 b = __half22float2(u2h(v.y));
    float2 c = __half22float2(u2h(v.z));
    float2 d = __half22float2(u2h(v.w));
    f[0] = a.x; f[1] = a.y; f[2] = b.x; f[3] = b.y;
    f[4] = c.x; f[5] = c.y; f[6] = d.x; f[7] = d.y;
}
__device__ __forceinline__ uint4 pack8(const float* f) {
    uint4 v;
    v.x = h2u(__float22half2_rn(make_float2(f[0], f[1])));
    v.y = h2u(__float22half2_rn(make_float2(f[2], f[3])));
    v.z = h2u(__float22half2_rn(make_float2(f[4], f[5])));
    v.w = h2u(__float22half2_rn(make_float2(f[6], f[7])));
    return v;
}
// ac += 2*(r0+r1) ; HADD2 pair, convert, FFMA-imm(2.0) accumulate
__device__ __forceinline__ void acc_pair(uint4 r0, uint4 r1, float* ac) {
    __half2 p0 = __hadd2(u2h(r0.x), u2h(r1.x));
    __half2 p1 = __hadd2(u2h(r0.y), u2h(r1.y));
    __half2 p2 = __hadd2(u2h(r0.z), u2h(r1.z));
    __half2 p3 = __hadd2(u2h(r0.w), u2h(r1.w));
    float2 f0 = __half22float2(p0);
    float2 f1 = __half22float2(p1);
    float2 f2 = __half22float2(p2);
    float2 f3 = __half22float2(p3);
    ac[0] = fmaf(f0.x, 2.0f, ac[0]); ac[1] = fmaf(f0.y, 2.0f, ac[1]);
    ac[2] = fmaf(f1.x, 2.0f, ac[2]); ac[3] = fmaf(f1.y, 2.0f, ac[3]);
    ac[4] = fmaf(f2.x, 2.0f, ac[4]); ac[5] = fmaf(f2.y, 2.0f, ac[5]);
    ac[6] = fmaf(f3.x, 2.0f, ac[6]); ac[7] = fmaf(f3.y, 2.0f, ac[7]);
}

// ---------------- setup kernels ----------------
__global__ void init_k(int n) {
    int i = blockIdx.x * blockDim.x + threadIdx.x;
    if (i < n) { g_indeg[i] = 0; g_cursor[i] = 0; }
}

// edge_index is int32; vectorized int4 over dst half
__global__ void hist_k(const int* __restrict__ ei, int e) {
    int i = blockIdx.x * blockDim.x + threadIdx.x;
    const int4* d4 = (const int4*)(ei + e);
    int q = e >> 2;
    if (i < q) {
        int4 d = d4[i];
        atomicAdd(&g_indeg[d.x], 1); atomicAdd(&g_indeg[d.y], 1);
        atomicAdd(&g_indeg[d.z], 1); atomicAdd(&g_indeg[d.w], 1);
    }
    int r = q * 4 + i;
    if (i < (e & 3) && r < e) atomicAdd(&g_indeg[ei[e + r]], 1);
}

// scan + dinv fused
__global__ void scan_blocks_k(int n) {
    __shared__ int sh[SCAN_B];
    int i = blockIdx.x * SCAN_B + threadIdx.x;
    int v = (i < n) ? g_indeg[i] : 0;
    if (i < n) g_dinv[i] = rsqrtf((float)(v + 1));
    sh[threadIdx.x] = v;
    __syncthreads();
    for (int off = 1; off < SCAN_B; off <<= 1) {
        int t = (threadIdx.x >= off) ? sh[threadIdx.x - off] : 0;
        __syncthreads();
        sh[threadIdx.x] += t;
        __syncthreads();
    }
    int incl = sh[threadIdx.x];
    if (i < n) g_rowptr[i] = incl - v;
    if (threadIdx.x == SCAN_B - 1) g_bsum[blockIdx.x] = incl;
}

__global__ void scan_bsums_k(int nb) {
    if (threadIdx.x == 0 && blockIdx.x == 0) {
        int acc = 0;
        for (int i = 0; i < nb; i++) { int v = g_bsum[i]; g_bsum[i] = acc; acc += v; }
    }
}

__global__ void add_offsets_k(int n, int e) {
    int i = blockIdx.x * SCAN_B + threadIdx.x;
    if (i < n) g_rowptr[i] += g_bsum[blockIdx.x];
    if (i == 0) g_rowptr[n] = e;
}

__global__ void scatter_k(const int* __restrict__ ei, int e) {
    int i = blockIdx.x * blockDim.x + threadIdx.x;
    const int4* s4 = (const int4*)ei;
    const int4* d4 = (const int4*)(ei + e);
    int q = e >> 2;
    if (i < q) {
        int4 s = s4[i], d = d4[i];
        g_csrc[g_rowptr[d.x] + atomicAdd(&g_cursor[d.x], 1)] = s.x;
        g_csrc[g_rowptr[d.y] + atomicAdd(&g_cursor[d.y], 1)] = s.y;
        g_csrc[g_rowptr[d.z] + atomicAdd(&g_cursor[d.z], 1)] = s.z;
        g_csrc[g_rowptr[d.w] + atomicAdd(&g_cursor[d.w], 1)] = s.w;
    }
    int r = q * 4 + i;
    if (i < (e & 3) && r < e) {
        int s = ei[r], d = ei[e + r];
        g_csrc[g_rowptr[d] + atomicAdd(&g_cursor[d], 1)] = s;
    }
}

__global__ void bn_pre_k(const float* b, const float* g, const float* be,
                         const float* rm, const float* rv, int d) {
    int i = threadIdx.x;
    if (i < d) {
        float s = g[i] * rsqrtf(rv[i] + EPS);
        g_bnS[i] = s;
        g_bnT[i] = (b[i] - rm[i]) * s + be[i];
    }
}

// ---------------- GEMM ----------------
// EPI: 0 = acc*dinv -> half     (L1)
//      1 = ELU(BN(acc+b))*dinv -> half   (L2)
//      2 = ELU(BN(acc+b)) -> float      (L3)
template <int DIN, int DOUT, int EPI, bool IN_HALF>
__global__ void gemm_k(const void* __restrict__ h_, const float* __restrict__ W,
                       const float* __restrict__ b, const float* __restrict__ g,
                       const float* __restrict__ be, const float* __restrict__ rm,
                       const float* __restrict__ rv, void* __restrict__ out_, int n) {
    constexpr int RPB = 256 / DOUT;
    __shared__ float Ws[DIN * DOUT];
    __shared__ float Hs[RPB][DIN];
    for (int i = threadIdx.x; i < DIN * DOUT / 4; i += 256)
        ((float4*)Ws)[i] = ((const float4*)W)[i];
    int r0 = blockIdx.x * RPB;
    if (IN_HALF) {
        constexpr int CPR = DIN / 8;     // 16B chunks per row
        const uint4* h4 = (const uint4*)h_;
        for (int c = threadIdx.x; c < RPB * CPR; c += 256) {
            int rr = c / CPR, cc = c % CPR;
            int grow = r0 + rr;
            float f[8];
            if (grow < n) { uint4 v = h4[(size_t)grow * CPR + cc]; cvt8(v, f); }
            else { for (int j = 0; j < 8; j++) f[j] = 0.f; }
            for (int j = 0; j < 8; j++) Hs[rr][cc * 8 + j] = f[j];
        }
    } else {
        constexpr int CPR = DIN / 4;
        const float4* h4 = (const float4*)h_;
        for (int c = threadIdx.x; c < RPB * CPR; c += 256) {
            int rr = c / CPR, cc = c % CPR;
            int grow = r0 + rr;
            float4 v = (grow < n) ? h4[(size_t)grow * CPR + cc]
                                  : make_float4(0.f, 0.f, 0.f, 0.f);
            Hs[rr][cc * 4 + 0] = v.x; Hs[rr][cc * 4 + 1] = v.y;
            Hs[rr][cc * 4 + 2] = v.z; Hs[rr][cc * 4 + 3] = v.w;
        }
    }
    __syncthreads();
    int f = threadIdx.x % DOUT;
    int r = threadIdx.x / DOUT;
    int row = r0 + r;
    float acc = 0.f;
#pragma unroll
    for (int k = 0; k < DIN; k++) acc += Hs[r][k] * Ws[k * DOUT + f];
    if (row >= n) return;
    if (EPI == 0) {
        ((__half*)out_)[(size_t)row * DOUT + f] = __float2half(acc * g_dinv[row]);
    } else {
        float v = acc + b[f];
        v = (v - rm[f]) * rsqrtf(rv[f] + EPS) * g[f] + be[f];
        v = (v > 0.f) ? v : expm1f(v);
        if (EPI == 1)
            ((__half*)out_)[(size_t)row * DOUT + f] = __float2half(v * g_dinv[row]);
        else
            ((float*)out_)[(size_t)row * DOUT + f] = v;
    }
}

// layer 4: 128 -> 1, warp per row, float4 lanes; out = acc*dinv
__global__ void gemm4_k(const float* __restrict__ h, const float* __restrict__ W,
                        float* __restrict__ out, int n) {
    int warp = (blockIdx.x * blockDim.x + threadIdx.x) >> 5;
    int lane = threadIdx.x & 31;
    if (warp >= n) return;
    float4 hv = ((const float4*)h)[(size_t)warp * 32 + lane];
    float4 wv = __ldg(&((const float4*)W)[lane]);
    float acc = hv.x * wv.x + hv.y * wv.y + hv.z * wv.z + hv.w * wv.w;
#pragma unroll
    for (int off = 16; off; off >>= 1) acc += __shfl_down_sync(0xffffffffu, acc, off);
    if (lane == 0) out[warp] = acc * g_dinv[warp];
}

// ---------------- aggregation over CSR (half rows, TPN threads/node) ----------------
// rows pre-scaled by dinv[src]; result = dinv[node]*(self + sum)
// EPI 0: store result (half). EPI 1: apply fused BN (g_bnS/g_bnT), ELU, *dinv, store half.
template <int TPN, int EPI>
__global__ void agg_h_k(const __half* __restrict__ in_, __half* __restrict__ out_, int n) {
    const uint4* in4 = (const uint4*)in_;
    uint4* out4 = (uint4*)out_;
    int tid = blockIdx.x * 256 + threadIdx.x;
    int node = tid / TPN, f = tid % TPN;
    if (node >= n) return;
    float di = g_dinv[node];
    float se[8], ac[8];
    cvt8(in4[(size_t)node * TPN + f], se);
#pragma unroll
    for (int j = 0; j < 8; j++) ac[j] = 0.f;
    int e0 = g_rowptr[node], e1 = g_rowptr[node + 1];
    int e = e0;
    for (; e + 1 < e1; e += 2) {
        int s0 = g_csrc[e], s1 = g_csrc[e + 1];
        uint4 r0 = in4[(size_t)s0 * TPN + f];
        uint4 r1 = in4[(size_t)s1 * TPN + f];
        acc_pair(r0, r1, ac);
    }
    if (e < e1) {
        float tmp[8];
        cvt8(in4[(size_t)g_csrc[e] * TPN + f], tmp);
#pragma unroll
        for (int j = 0; j < 8; j++) se[j] += tmp[j];
    }
    float v[8];
#pragma unroll
    for (int j = 0; j < 8; j++) v[j] = fmaf(ac[j], 0.5f, se[j]) * di;
    if (EPI == 1) {
        float4 sA = ((const float4*)g_bnS)[f * 2];
        float4 sB = ((const float4*)g_bnS)[f * 2 + 1];
        float4 tA = ((const float4*)g_bnT)[f * 2];
        float4 tB = ((const float4*)g_bnT)[f * 2 + 1];
        float s[8] = {sA.x, sA.y, sA.z, sA.w, sB.x, sB.y, sB.z, sB.w};
        float t[8] = {tA.x, tA.y, tA.z, tA.w, tB.x, tB.y, tB.z, tB.w};
#pragma unroll
        for (int j = 0; j < 8; j++) {
            float u = v[j] * s[j] + t[j];
            u = (u > 0.f) ? u : expm1f(u);
            v[j] = u * di;
        }
    }
    out4[(size_t)node * TPN + f] = pack8(v);
}

// last layer: scalar rows; v = di*(self+sum)+b, ELU, sigmoid
__global__ void agg_last_k(const float* __restrict__ in, const float* __restrict__ b,
                           float* __restrict__ out, int n) {
    int node = blockIdx.x * blockDim.x + threadIdx.x;
    if (node >= n) return;
    float di = g_dinv[node];
    float a0 = in[node], a1 = 0.f;
    int e0 = g_rowptr[node], e1 = g_rowptr[node + 1];
    int e = e0;
    for (; e + 1 < e1; e += 2) {
        a0 += in[g_csrc[e]];
        a1 += in[g_csrc[e + 1]];
    }
    if (e < e1) a0 += in[g_csrc[e]];
    float v = (a0 + a1) * di + b[0];
    v = (v > 0.f) ? v : expm1f(v);
    out[node] = 1.f / (1.f + expf(-v));
}

// ---------------- launch ----------------
extern "C" void kernel_launch(void* const* d_in, const int* in_sizes, int n_in,
                              void* d_out, int out_size) {
    const float* x  = (const float*)d_in[0];
    const int*   ei = (const int*)d_in[1];
    const float* W1 = (const float*)d_in[2];  const float* b1 = (const float*)d_in[3];
    const float* W2 = (const float*)d_in[4];  const float* b2 = (const float*)d_in[5];
    const float* W3 = (const float*)d_in[6];  const float* b3 = (const float*)d_in[7];
    const float* W4 = (const float*)d_in[8];  const float* b4 = (const float*)d_in[9];
    const float* g1 = (const float*)d_in[10]; const float* be1 = (const float*)d_in[11];
    const float* rm1 = (const float*)d_in[12]; const float* rv1 = (const float*)d_in[13];
    const float* g2 = (const float*)d_in[14]; const float* be2 = (const float*)d_in[15];
    const float* rm2 = (const float*)d_in[16]; const float* rv2 = (const float*)d_in[17];
    const float* g3 = (const float*)d_in[18]; const float* be3 = (const float*)d_in[19];
    const float* rm3 = (const float*)d_in[20]; const float* rv3 = (const float*)d_in[21];

    int n = in_sizes[0] / 64;       // 100000
    int e = in_sizes[1] / 2;        // 1600000

    __half* hA; cudaGetSymbolAddress((void**)&hA, g_hA);
    __half* hB; cudaGetSymbolAddress((void**)&hB, g_hB);
    float* f32; cudaGetSymbolAddress((void**)&f32, g_f32);
    float* scal; cudaGetSymbolAddress((void**)&scal, g_scal);
    float* out = (float*)d_out;

    int nb_n  = (n + 255) / 256;
    int nb_e4 = (e / 4 + 255) / 256;
    int nb_sc = (n + SCAN_B - 1) / SCAN_B;

    // CSR build (scatter deferred after gemm1 so ncu -s 5 lands on gemm1)
    init_k<<<nb_n, 256>>>(n);
    hist_k<<<nb_e4, 256>>>(ei, e);
    scan_blocks_k<<<nb_sc, SCAN_B>>>(n);      // + dinv
    scan_bsums_k<<<1, 32>>>(nb_sc);
    add_offsets_k<<<nb_sc, SCAN_B>>>(n, e);

    // layer 1 transform: x(f32,64) @ W1 -> *dinv -> hA (half w32)
    gemm_k<64, 32, 0, false><<<(n + 7) / 8, 256>>>(x, W1, 0, 0, 0, 0, 0, hA, n);

    scatter_k<<<nb_e4, 256>>>(ei, e);
    bn_pre_k<<<1, 32>>>(b1, g1, be1, rm1, rv1, 32);

    // layer 1 agg (+fused BN/ELU, *dinv): hA -> hB (half w32)
    agg_h_k<4, 1><<<(n * 4 + 255) / 256, 256>>>(hA, hB, n);

    // layer 2: agg first (w32), then transform 32->64 (+BN/ELU, *dinv)
    agg_h_k<4, 0><<<(n * 4 + 255) / 256, 256>>>(hB, hA, n);
    gemm_k<32, 64, 1, true><<<(n + 3) / 4, 256>>>(hA, W2, b2, g2, be2, rm2, rv2, hB, n);

    // layer 3: agg first (w64), then transform 64->128 (+BN/ELU) -> f32
    agg_h_k<8, 0><<<(n * 8 + 255) / 256, 256>>>(hB, hA, n);
    gemm_k<64, 128, 2, true><<<(n + 1) / 2, 256>>>(hA, W3, b3, g3, be3, rm3, rv3, f32, n);

    // layer 4: 128->1 (*dinv), agg + ELU + sigmoid
    gemm4_k<<<(n * 32 + 255) / 256, 256>>>(f32, W4, scal, n);
    agg_last_k<<<nb_n, 256>>>(scal, b4, out, n);
}

// round 6
// speedup vs baseline: 1.9847x; 1.3741x over previous
#include <cuda_runtime.h>
#include <cuda_fp16.h>
#include <math.h>

#define MAXN 100096
#define MAXE 1600512
#define SCAN_B 1024
#define EPS 1e-5f

// ---------------- static scratch ----------------
__device__ int    g_indeg[MAXN];
__device__ int    g_cursor[MAXN];
__device__ int    g_rowptr[MAXN + 1];
__device__ int    g_bsum[1024];
__device__ float  g_dinv[MAXN];
__device__ int    g_csrc[MAXE];
__device__ __half g_hA[MAXN * 64];
__device__ __half g_hB[MAXN * 64];
__device__ __half g_hC[MAXN * 128];
__device__ float  g_scal[MAXN];
__device__ float  g_bnS[32];
__device__ float  g_bnT[32];

// ---------------- half helpers ----------------
__device__ __forceinline__ __half2 u2h(unsigned u) {
    __half2 h; *reinterpret_cast<unsigned*>(&h) = u; return h;
}
__device__ __forceinline__ unsigned h2u(__half2 h) {
    return *reinterpret_cast<unsigned*>(&h);
}
__device__ __forceinline__ void cvt8(uint4 v, float* f) {
    float2 a = __half22float2(u2h(v.x));
    float2 b = __half22float2(u2h(v.y));
    float2 c = __half22float2(u2h(v.z));
    float2 d = __half22float2(u2h(v.w));
    f[0] = a.x; f[1] = a.y; f[2] = b.x; f[3] = b.y;
    f[4] = c.x; f[5] = c.y; f[6] = d.x; f[7] = d.y;
}

// ---------------- setup kernels ----------------
__global__ void init_k(int n) {
    int i = blockIdx.x * blockDim.x + threadIdx.x;
    if (i < n) { g_indeg[i] = 0; g_cursor[i] = 0; }
}

__global__ void hist_k(const int* __restrict__ ei, int e) {
    int i = blockIdx.x * blockDim.x + threadIdx.x;
    const int4* d4 = (const int4*)(ei + e);
    int q = e >> 2;
    if (i < q) {
        int4 d = d4[i];
        atomicAdd(&g_indeg[d.x], 1); atomicAdd(&g_indeg[d.y], 1);
        atomicAdd(&g_indeg[d.z], 1); atomicAdd(&g_indeg[d.w], 1);
    }
    int r = q * 4 + i;
    if (i < (e & 3) && r < e) atomicAdd(&g_indeg[ei[e + r]], 1);
}

__global__ void scan_blocks_k(int n) {
    __shared__ int sh[SCAN_B];
    int i = blockIdx.x * SCAN_B + threadIdx.x;
    int v = (i < n) ? g_indeg[i] : 0;
    if (i < n) g_dinv[i] = rsqrtf((float)(v + 1));
    sh[threadIdx.x] = v;
    __syncthreads();
    for (int off = 1; off < SCAN_B; off <<= 1) {
        int t = (threadIdx.x >= off) ? sh[threadIdx.x - off] : 0;
        __syncthreads();
        sh[threadIdx.x] += t;
        __syncthreads();
    }
    int incl = sh[threadIdx.x];
    if (i < n) g_rowptr[i] = incl - v;
    if (threadIdx.x == SCAN_B - 1) g_bsum[blockIdx.x] = incl;
}

// warp-level scan of block sums (nb <= 128)
__global__ void scan_bsums_k(int nb) {
    int lane = threadIdx.x;     // 32 threads
    int base = lane * 4;
    int v[4];
#pragma unroll
    for (int j = 0; j < 4; j++) v[j] = (base + j < nb) ? g_bsum[base + j] : 0;
    int ls = v[0] + v[1] + v[2] + v[3];
    int run = ls;
#pragma unroll
    for (int off = 1; off < 32; off <<= 1) {
        int t = __shfl_up_sync(0xffffffffu, run, off);
        if (lane >= off) run += t;
    }
    int excl = run - ls;
#pragma unroll
    for (int j = 0; j < 4; j++) {
        if (base + j < nb) g_bsum[base + j] = excl;
        excl += v[j];
    }
}

__global__ void add_offsets_k(int n, int e) {
    int i = blockIdx.x * SCAN_B + threadIdx.x;
    if (i < n) g_rowptr[i] += g_bsum[blockIdx.x];
    if (i == 0) g_rowptr[n] = e;
}

__global__ void scatter_k(const int* __restrict__ ei, int e) {
    int i = blockIdx.x * blockDim.x + threadIdx.x;
    const int4* s4 = (const int4*)ei;
    const int4* d4 = (const int4*)(ei + e);
    int q = e >> 2;
    if (i < q) {
        int4 s = s4[i], d = d4[i];
        g_csrc[g_rowptr[d.x] + atomicAdd(&g_cursor[d.x], 1)] = s.x;
        g_csrc[g_rowptr[d.y] + atomicAdd(&g_cursor[d.y], 1)] = s.y;
        g_csrc[g_rowptr[d.z] + atomicAdd(&g_cursor[d.z], 1)] = s.z;
        g_csrc[g_rowptr[d.w] + atomicAdd(&g_cursor[d.w], 1)] = s.w;
    }
    int r = q * 4 + i;
    if (i < (e & 3) && r < e) {
        int s = ei[r], d = ei[e + r];
        g_csrc[g_rowptr[d] + atomicAdd(&g_cursor[d], 1)] = s;
    }
}

__global__ void bn_pre_k(const float* b, const float* g, const float* be,
                         const float* rm, const float* rv, int d) {
    int i = threadIdx.x;
    if (i < d) {
        float s = g[i] * rsqrtf(rv[i] + EPS);
        g_bnS[i] = s;
        g_bnT[i] = (b[i] - rm[i]) * s + be[i];
    }
}

// ---------------- GEMM: 4 outputs per thread ----------------
// EPI: 0 = acc*dinv         (L1 pre-agg)
//      1 = ELU(BN(acc+b))*dinv   (L2 output)
//      2 = ELU(BN(acc+b))        (L3 output)
template <int DIN, int DOUT, int EPI, bool IN_HALF, bool OUT_HALF>
__global__ void gemm_k(const void* __restrict__ h_, const float* __restrict__ W,
                       const float* __restrict__ b, const float* __restrict__ g,
                       const float* __restrict__ be, const float* __restrict__ rm,
                       const float* __restrict__ rv, void* __restrict__ out_, int n) {
    constexpr int TPR = DOUT / 4;
    constexpr int RPB = 256 / TPR;
    __shared__ float Ws[DIN * DOUT];
    __shared__ float Hs[RPB][DIN];
    for (int i = threadIdx.x; i < DIN * DOUT / 4; i += 256)
        ((float4*)Ws)[i] = ((const float4*)W)[i];
    int r0 = blockIdx.x * RPB;
    if (IN_HALF) {
        constexpr int CPR = DIN / 8;
        const uint4* h4 = (const uint4*)h_;
        for (int c = threadIdx.x; c < RPB * CPR; c += 256) {
            int rr = c / CPR, cc = c % CPR;
            int grow = r0 + rr;
            float f[8];
            if (grow < n) { cvt8(h4[(size_t)grow * CPR + cc], f); }
            else { for (int j = 0; j < 8; j++) f[j] = 0.f; }
            for (int j = 0; j < 8; j++) Hs[rr][cc * 8 + j] = f[j];
        }
    } else {
        constexpr int CPR = DIN / 4;
        const float4* h4 = (const float4*)h_;
        for (int c = threadIdx.x; c < RPB * CPR; c += 256) {
            int rr = c / CPR, cc = c % CPR;
            int grow = r0 + rr;
            float4 v = (grow < n) ? h4[(size_t)grow * CPR + cc]
                                  : make_float4(0.f, 0.f, 0.f, 0.f);
            Hs[rr][cc * 4 + 0] = v.x; Hs[rr][cc * 4 + 1] = v.y;
            Hs[rr][cc * 4 + 2] = v.z; Hs[rr][cc * 4 + 3] = v.w;
        }
    }
    __syncthreads();
    int fq = threadIdx.x % TPR;
    int r  = threadIdx.x / TPR;
    int row = r0 + r;
    float4 acc = make_float4(0.f, 0.f, 0.f, 0.f);
#pragma unroll
    for (int k = 0; k < DIN; k++) {
        float hk = Hs[r][k];
        float4 w = ((const float4*)Ws)[k * TPR + fq];
        acc.x = fmaf(hk, w.x, acc.x);
        acc.y = fmaf(hk, w.y, acc.y);
        acc.z = fmaf(hk, w.z, acc.z);
        acc.w = fmaf(hk, w.w, acc.w);
    }
    if (row >= n) return;
    int fb = fq * 4;
    float v[4] = {acc.x, acc.y, acc.z, acc.w};
    if (EPI >= 1) {
#pragma unroll
        for (int j = 0; j < 4; j++) {
            float u = v[j] + __ldg(&b[fb + j]);
            u = (u - __ldg(&rm[fb + j])) * rsqrtf(__ldg(&rv[fb + j]) + EPS) * __ldg(&g[fb + j]) + __ldg(&be[fb + j]);
            v[j] = (u > 0.f) ? u : expm1f(u);
        }
    }
    if (EPI == 0 || EPI == 1) {
        float di = g_dinv[row];
#pragma unroll
        for (int j = 0; j < 4; j++) v[j] *= di;
    }
    if (OUT_HALF) {
        uint2 o;
        o.x = h2u(__float22half2_rn(make_float2(v[0], v[1])));
        o.y = h2u(__float22half2_rn(make_float2(v[2], v[3])));
        ((uint2*)out_)[(size_t)row * TPR + fq] = o;
    } else {
        ((float4*)out_)[(size_t)row * TPR + fq] = make_float4(v[0], v[1], v[2], v[3]);
    }
}

// layer 4: 128(half) -> 1, warp per row; out = acc*dinv
__global__ void gemm4_k(const __half* __restrict__ h, const float* __restrict__ W,
                        float* __restrict__ out, int n) {
    int warp = (blockIdx.x * blockDim.x + threadIdx.x) >> 5;
    int lane = threadIdx.x & 31;
    if (warp >= n) return;
    uint2 hv = ((const uint2*)h)[(size_t)warp * 32 + lane];
    float2 h01 = __half22float2(u2h(hv.x));
    float2 h23 = __half22float2(u2h(hv.y));
    float4 wv = __ldg(&((const float4*)W)[lane]);
    float acc = h01.x * wv.x + h01.y * wv.y + h23.x * wv.z + h23.y * wv.w;
#pragma unroll
    for (int off = 16; off; off >>= 1) acc += __shfl_down_sync(0xffffffffu, acc, off);
    if (lane == 0) out[warp] = acc * g_dinv[warp];
}

// ---------------- aggregation (half rows, TPN threads/node, batch-8 MLP) ----------------
// rows pre-scaled by dinv[src]; result = dinv[node]*(self + sum)
// EPI 0: store half. EPI 1: fused BN (g_bnS/T), ELU, *dinv, store half.
template <int TPN, int EPI>
__global__ void agg_h_k(const __half* __restrict__ in_, __half* __restrict__ out_, int n) {
    constexpr int NB = 8 / TPN;      // csrc loads per thread per batch of 8 edges
    const uint4* in4 = (const uint4*)in_;
    uint4* out4 = (uint4*)out_;
    int tid = blockIdx.x * 256 + threadIdx.x;
    int node = tid / TPN, f = tid % TPN;
    if (node >= n) return;
    int lane = threadIdx.x & 31;
    int segbase = lane & ~(TPN - 1);
    unsigned mask = ((1u << TPN) - 1u) << segbase;
    float di = g_dinv[node];
    uint4 sv = in4[(size_t)node * TPN + f];
    __half2 a0 = u2h(sv.x), a1 = u2h(sv.y), a2 = u2h(sv.z), a3 = u2h(sv.w);
    __half2 z = __float2half2_rn(0.f);
    __half2 c0 = z, c1 = z, c2 = z, c3 = z;
    int e0 = g_rowptr[node], e1 = g_rowptr[node + 1];
    int e = e0;
    for (; e + 8 <= e1; e += 8) {
        int sl[NB];
#pragma unroll
        for (int j = 0; j < NB; j++) sl[j] = g_csrc[e + j * TPN + f];
        uint4 r[8];
#pragma unroll
        for (int k = 0; k < 8; k++) {
            int sk = __shfl_sync(mask, sl[k / TPN], segbase + (k % TPN), 32);
            r[k] = in4[(size_t)sk * TPN + f];
        }
#pragma unroll
        for (int k = 0; k < 8; k += 2) {
            a0 = __hadd2(a0, u2h(r[k].x));     c0 = __hadd2(c0, u2h(r[k + 1].x));
            a1 = __hadd2(a1, u2h(r[k].y));     c1 = __hadd2(c1, u2h(r[k + 1].y));
            a2 = __hadd2(a2, u2h(r[k].z));     c2 = __hadd2(c2, u2h(r[k + 1].z));
            a3 = __hadd2(a3, u2h(r[k].w));     c3 = __hadd2(c3, u2h(r[k + 1].w));
        }
    }
    for (; e < e1; e++) {
        int s = g_csrc[e];
        uint4 r = in4[(size_t)s * TPN + f];
        a0 = __hadd2(a0, u2h(r.x)); a1 = __hadd2(a1, u2h(r.y));
        a2 = __hadd2(a2, u2h(r.z)); a3 = __hadd2(a3, u2h(r.w));
    }
    // combine chains in fp32
    float v[8];
    {
        float2 p, q;
        p = __half22float2(a0); q = __half22float2(c0); v[0] = p.x + q.x; v[1] = p.y + q.y;
        p = __half22float2(a1); q = __half22float2(c1); v[2] = p.x + q.x; v[3] = p.y + q.y;
        p = __half22float2(a2); q = __half22float2(c2); v[4] = p.x + q.x; v[5] = p.y + q.y;
        p = __half22float2(a3); q = __half22float2(c3); v[6] = p.x + q.x; v[7] = p.y + q.y;
    }
#pragma unroll
    for (int j = 0; j < 8; j++) v[j] *= di;
    if (EPI == 1) {
        float4 sA = ((const float4*)g_bnS)[f * 2];
        float4 sB = ((const float4*)g_bnS)[f * 2 + 1];
        float4 tA = ((const float4*)g_bnT)[f * 2];
        float4 tB = ((const float4*)g_bnT)[f * 2 + 1];
        float s[8] = {sA.x, sA.y, sA.z, sA.w, sB.x, sB.y, sB.z, sB.w};
        float t[8] = {tA.x, tA.y, tA.z, tA.w, tB.x, tB.y, tB.z, tB.w};
#pragma unroll
        for (int j = 0; j < 8; j++) {
            float u = v[j] * s[j] + t[j];
            u = (u > 0.f) ? u : expm1f(u);
            v[j] = u * di;
        }
    }
    uint4 o;
    o.x = h2u(__float22half2_rn(make_float2(v[0], v[1])));
    o.y = h2u(__float22half2_rn(make_float2(v[2], v[3])));
    o.z = h2u(__float22half2_rn(make_float2(v[4], v[5])));
    o.w = h2u(__float22half2_rn(make_float2(v[6], v[7])));
    out4[(size_t)node * TPN + f] = o;
}

// last layer: scalar rows, batch-4; v = di*(self+sum)+b, ELU, sigmoid
__global__ void agg_last_k(const float* __restrict__ in, const float* __restrict__ b,
                           float* __restrict__ out, int n) {
    int node = blockIdx.x * blockDim.x + threadIdx.x;
    if (node >= n) return;
    float di = g_dinv[node];
    float a0 = in[node], a1 = 0.f, a2 = 0.f, a3 = 0.f;
    int e0 = g_rowptr[node], e1 = g_rowptr[node + 1];
    int e = e0;
    for (; e + 4 <= e1; e += 4) {
        int s0 = g_csrc[e], s1 = g_csrc[e + 1], s2 = g_csrc[e + 2], s3 = g_csrc[e + 3];
        a0 += in[s0]; a1 += in[s1]; a2 += in[s2]; a3 += in[s3];
    }
    for (; e < e1; e++) a0 += in[g_csrc[e]];
    float v = ((a0 + a1) + (a2 + a3)) * di + b[0];
    v = (v > 0.f) ? v : expm1f(v);
    out[node] = 1.f / (1.f + expf(-v));
}

// ---------------- launch ----------------
extern "C" void kernel_launch(void* const* d_in, const int* in_sizes, int n_in,
                              void* d_out, int out_size) {
    const float* x  = (const float*)d_in[0];
    const int*   ei = (const int*)d_in[1];
    const float* W1 = (const float*)d_in[2];  const float* b1 = (const float*)d_in[3];
    const float* W2 = (const float*)d_in[4];  const float* b2 = (const float*)d_in[5];
    const float* W3 = (const float*)d_in[6];  const float* b3 = (const float*)d_in[7];
    const float* W4 = (const float*)d_in[8];  const float* b4 = (const float*)d_in[9];
    const float* g1 = (const float*)d_in[10]; const float* be1 = (const float*)d_in[11];
    const float* rm1 = (const float*)d_in[12]; const float* rv1 = (const float*)d_in[13];
    const float* g2 = (const float*)d_in[14]; const float* be2 = (const float*)d_in[15];
    const float* rm2 = (const float*)d_in[16]; const float* rv2 = (const float*)d_in[17];
    const float* g3 = (const float*)d_in[18]; const float* be3 = (const float*)d_in[19];
    const float* rm3 = (const float*)d_in[20]; const float* rv3 = (const float*)d_in[21];

    int n = in_sizes[0] / 64;       // 100000
    int e = in_sizes[1] / 2;        // 1600000

    __half* hA; cudaGetSymbolAddress((void**)&hA, g_hA);
    __half* hB; cudaGetSymbolAddress((void**)&hB, g_hB);
    __half* hC; cudaGetSymbolAddress((void**)&hC, g_hC);
    float* scal; cudaGetSymbolAddress((void**)&scal, g_scal);
    float* out = (float*)d_out;

    int nb_n  = (n + 255) / 256;
    int nb_e4 = (e / 4 + 255) / 256;
    int nb_sc = (n + SCAN_B - 1) / SCAN_B;

    // CSR build
    init_k<<<nb_n, 256>>>(n);
    hist_k<<<nb_e4, 256>>>(ei, e);
    scan_blocks_k<<<nb_sc, SCAN_B>>>(n);      // + dinv
    scan_bsums_k<<<1, 32>>>(nb_sc);
    add_offsets_k<<<nb_sc, SCAN_B>>>(n, e);

    // layer 1 transform: x(f32,64) @ W1 -> *dinv -> hA (half w32)
    gemm_k<64, 32, 0, false, true><<<(n + 31) / 32, 256>>>(x, W1, 0, 0, 0, 0, 0, hA, n);

    scatter_k<<<nb_e4, 256>>>(ei, e);
    bn_pre_k<<<1, 32>>>(b1, g1, be1, rm1, rv1, 32);

    // layer 1 agg (+fused BN/ELU, *dinv): hA -> hB (w32)
    agg_h_k<4, 1><<<(n * 4 + 255) / 256, 256>>>(hA, hB, n);

    // layer 2: agg first (w32), then transform 32->64 (+BN/ELU, *dinv)
    agg_h_k<4, 0><<<(n * 4 + 255) / 256, 256>>>(hB, hA, n);
    gemm_k<32, 64, 1, true, true><<<(n + 15) / 16, 256>>>(hA, W2, b2, g2, be2, rm2, rv2, hB, n);

    // layer 3: agg first (w64), then transform 64->128 (+BN/ELU) -> half
    agg_h_k<8, 0><<<(n * 8 + 255) / 256, 256>>>(hB, hA, n);
    gemm_k<64, 128, 2, true, true><<<(n + 7) / 8, 256>>>(hA, W3, b3, g3, be3, rm3, rv3, hC, n);

    // layer 4: 128->1 (*dinv), agg + ELU + sigmoid
    gemm4_k<<<(n * 32 + 255) / 256, 256>>>(hC, W4, scal, n);
    agg_last_k<<<nb_n, 256>>>(scal, b4, out, n);
}

// round 7
// speedup vs baseline: 3.9346x; 1.9825x over previous
#include <cuda_runtime.h>
#include <cuda_fp16.h>
#include <math.h>

#define MAXN 100096
#define MAXE 1600512
#define EPS 1e-5f

// ---------------- static scratch ----------------
__device__ int    g_indeg[MAXN];
__device__ int    g_cursor[MAXN];
__device__ int    g_start[MAXN];
__device__ int    g_ctr;
__device__ float  g_dinv[MAXN];
__device__ int    g_csrc[MAXE];
__device__ __half g_hA[MAXN * 64];
__device__ __half g_hB[MAXN * 64];
__device__ __half g_hC[MAXN * 128];
__device__ float  g_scal[MAXN];
__device__ float  g_bnS1[32],  g_bnT1[32];
__device__ float  g_bnS2[64],  g_bnT2[64];
__device__ float  g_bnS3[128], g_bnT3[128];
__device__ uint2  g_w1f[4 * 4 * 32];    // NT=4,  KC=4
__device__ uint2  g_w2f[8 * 2 * 32];    // NT=8,  KC=2
__device__ uint2  g_w3f[16 * 4 * 32];   // NT=16, KC=4

// ---------------- half helpers ----------------
__device__ __forceinline__ __half2 u2h(unsigned u) {
    __half2 h; *reinterpret_cast<unsigned*>(&h) = u; return h;
}
__device__ __forceinline__ unsigned h2u(__half2 h) {
    return *reinterpret_cast<unsigned*>(&h);
}

// ---------------- setup kernels ----------------
__global__ void init_k(int n) {
    int i = blockIdx.x * blockDim.x + threadIdx.x;
    if (i < n) { g_indeg[i] = 0; g_cursor[i] = 0; }
    if (i == 0) g_ctr = 0;
}

__global__ void hist_k(const int* __restrict__ ei, int e) {
    int i = blockIdx.x * blockDim.x + threadIdx.x;
    const int4* d4 = (const int4*)(ei + e);
    int q = e >> 2;
    if (i < q) {
        int4 d = d4[i];
        atomicAdd(&g_indeg[d.x], 1); atomicAdd(&g_indeg[d.y], 1);
        atomicAdd(&g_indeg[d.z], 1); atomicAdd(&g_indeg[d.w], 1);
    }
    int r = q * 4 + i;
    if (i < (e & 3) && r < e) atomicAdd(&g_indeg[ei[e + r]], 1);
}

// segment-start assignment: warp scan + one atomic per warp (order irrelevant)
__global__ void assign_k(int n) {
    int i = blockIdx.x * blockDim.x + threadIdx.x;
    int lane = threadIdx.x & 31;
    int deg = (i < n) ? g_indeg[i] : 0;
    if (i < n) g_dinv[i] = rsqrtf((float)(deg + 1));
    int run = deg;
#pragma unroll
    for (int off = 1; off < 32; off <<= 1) {
        int t = __shfl_up_sync(0xffffffffu, run, off);
        if (lane >= off) run += t;
    }
    int total = __shfl_sync(0xffffffffu, run, 31);
    int base = 0;
    if (lane == 31) base = atomicAdd(&g_ctr, total);
    base = __shfl_sync(0xffffffffu, base, 31);
    if (i < n) g_start[i] = base + run - deg;
}

__global__ void scatter_k(const int* __restrict__ ei, int e) {
    int i = blockIdx.x * blockDim.x + threadIdx.x;
    const int4* s4 = (const int4*)ei;
    const int4* d4 = (const int4*)(ei + e);
    int q = e >> 2;
    if (i < q) {
        int4 s = s4[i], d = d4[i];
        g_csrc[g_start[d.x] + atomicAdd(&g_cursor[d.x], 1)] = s.x;
        g_csrc[g_start[d.y] + atomicAdd(&g_cursor[d.y], 1)] = s.y;
        g_csrc[g_start[d.z] + atomicAdd(&g_cursor[d.z], 1)] = s.z;
        g_csrc[g_start[d.w] + atomicAdd(&g_cursor[d.w], 1)] = s.w;
    }
    int r = q * 4 + i;
    if (i < (e & 3) && r < e) {
        int s = ei[r], d = ei[e + r];
        g_csrc[g_start[d] + atomicAdd(&g_cursor[d], 1)] = s;
    }
}

// weight fragments + BN tables, one kernel
__device__ __forceinline__ void make_frag(const float* __restrict__ W, int DOUT, int KC,
                                          uint2* __restrict__ dst, int i) {
    int nt = i / (KC * 32);
    int rem = i % (KC * 32);
    int kc = rem / 32, lane = rem % 32;
    int col = nt * 8 + (lane >> 2);
    int kb = kc * 16 + (lane & 3) * 2;
    uint2 o;
    o.x = h2u(__floats2half2_rn(W[kb * DOUT + col],       W[(kb + 1) * DOUT + col]));
    o.y = h2u(__floats2half2_rn(W[(kb + 8) * DOUT + col], W[(kb + 9) * DOUT + col]));
    dst[i] = o;
}
__device__ __forceinline__ void make_bn(const float* b, const float* g, const float* be,
                                        const float* rm, const float* rv,
                                        float* S, float* T, int j) {
    float s = g[j] * rsqrtf(rv[j] + EPS);
    S[j] = s;
    T[j] = (b[j] - rm[j]) * s + be[j];
}
__global__ void prep_k(const float* W1, const float* W2, const float* W3,
                       const float* b1, const float* g1, const float* be1, const float* rm1, const float* rv1,
                       const float* b2, const float* g2, const float* be2, const float* rm2, const float* rv2,
                       const float* b3, const float* g3, const float* be3, const float* rm3, const float* rv3) {
    int i = blockIdx.x * blockDim.x + threadIdx.x;
    if (i < 512)        make_frag(W1, 32,  4, g_w1f, i);
    else if (i < 1024)  make_frag(W2, 64,  2, g_w2f, i - 512);
    else if (i < 3072)  make_frag(W3, 128, 4, g_w3f, i - 1024);
    else if (i < 3104)  make_bn(b1, g1, be1, rm1, rv1, g_bnS1, g_bnT1, i - 3072);
    else if (i < 3168)  make_bn(b2, g2, be2, rm2, rv2, g_bnS2, g_bnT2, i - 3104);
    else if (i < 3296)  make_bn(b3, g3, be3, rm3, rv3, g_bnS3, g_bnT3, i - 3168);
}

// ---------------- tensor-core GEMM: 128 rows/block, mma.m16n8k16 ----------------
// EPI: 0 = acc*dinv (half out)   1 = ELU(BN(acc))*dinv   2 = ELU(BN(acc))
template <int DIN, int DOUT, int EPI, bool IN_HALF>
__global__ void gemm_mma_k(const void* __restrict__ in_, const uint2* __restrict__ wfrag,
                           const float* __restrict__ bnS, const float* __restrict__ bnT,
                           __half* __restrict__ out, int n) {
    constexpr int KC = DIN / 16;
    constexpr int NT = DOUT / 8;
    constexpr int STR = DIN + 4;                 // padded halves per row
    __shared__ __half As[128 * STR];
    __shared__ uint2  Bs[NT * KC * 32];
    int tid = threadIdx.x, wid = tid >> 5, lane = tid & 31;
    int rowbase = blockIdx.x * 128;

    for (int i = tid; i < NT * KC * 32; i += 256) Bs[i] = wfrag[i];

    if (IN_HALF) {
        constexpr int CPR = DIN / 8;             // uint4 per row
        const uint4* src = (const uint4*)in_;
        for (int c = tid; c < 128 * CPR; c += 256) {
            int r = c / CPR, q = c % CPR;
            uint4 v = (rowbase + r < n) ? src[(size_t)(rowbase + r) * CPR + q]
                                        : make_uint4(0, 0, 0, 0);
            __half* p = &As[r * STR + q * 8];
            ((uint2*)p)[0] = make_uint2(v.x, v.y);
            ((uint2*)p)[1] = make_uint2(v.z, v.w);
        }
    } else {
        constexpr int CPR = DIN / 4;             // float4 per row
        const float4* src = (const float4*)in_;
        for (int c = tid; c < 128 * CPR; c += 256) {
            int r = c / CPR, q = c % CPR;
            float4 v = (rowbase + r < n) ? src[(size_t)(rowbase + r) * CPR + q]
                                         : make_float4(0.f, 0.f, 0.f, 0.f);
            uint2 o;
            o.x = h2u(__floats2half2_rn(v.x, v.y));
            o.y = h2u(__floats2half2_rn(v.z, v.w));
            *(uint2*)&As[r * STR + q * 4] = o;
        }
    }
    __syncthreads();

    int g = lane >> 2, t = lane & 3;
    int r0 = wid * 16 + g;
    unsigned a[KC][4];
#pragma unroll
    for (int kc = 0; kc < KC; kc++) {
        int kb = kc * 16 + t * 2;
        a[kc][0] = *(const unsigned*)&As[r0 * STR + kb];
        a[kc][1] = *(const unsigned*)&As[(r0 + 8) * STR + kb];
        a[kc][2] = *(const unsigned*)&As[r0 * STR + kb + 8];
        a[kc][3] = *(const unsigned*)&As[(r0 + 8) * STR + kb + 8];
    }
    int grow0 = rowbase + r0, grow1 = grow0 + 8;
    float di0 = 1.f, di1 = 1.f;
    if (EPI <= 1) {
        di0 = (grow0 < n) ? g_dinv[grow0] : 0.f;
        di1 = (grow1 < n) ? g_dinv[grow1] : 0.f;
    }
#pragma unroll
    for (int nt = 0; nt < NT; nt++) {
        float c0 = 0.f, c1 = 0.f, c2 = 0.f, c3 = 0.f;
#pragma unroll
        for (int kc = 0; kc < KC; kc++) {
            uint2 b = Bs[(nt * KC + kc) * 32 + lane];
            asm volatile(
                "mma.sync.aligned.m16n8k16.row.col.f32.f16.f16.f32 "
                "{%0,%1,%2,%3}, {%4,%5,%6,%7}, {%8,%9}, {%0,%1,%2,%3};\n"
                : "+f"(c0), "+f"(c1), "+f"(c2), "+f"(c3)
                : "r"(a[kc][0]), "r"(a[kc][1]), "r"(a[kc][2]), "r"(a[kc][3]),
                  "r"(b.x), "r"(b.y));
        }
        int col = nt * 8 + t * 2;
        if (EPI >= 1) {
            float s0 = bnS[col], s1 = bnS[col + 1];
            float t0 = bnT[col], t1 = bnT[col + 1];
            c0 = c0 * s0 + t0; c1 = c1 * s1 + t1;
            c2 = c2 * s0 + t0; c3 = c3 * s1 + t1;
            c0 = (c0 > 0.f) ? c0 : expm1f(c0);
            c1 = (c1 > 0.f) ? c1 : expm1f(c1);
            c2 = (c2 > 0.f) ? c2 : expm1f(c2);
            c3 = (c3 > 0.f) ? c3 : expm1f(c3);
        }
        if (EPI <= 1) { c0 *= di0; c1 *= di0; c2 *= di1; c3 *= di1; }
        if (grow0 < n)
            *(unsigned*)&out[(size_t)grow0 * DOUT + col] = h2u(__floats2half2_rn(c0, c1));
        if (grow1 < n)
            *(unsigned*)&out[(size_t)grow1 * DOUT + col] = h2u(__floats2half2_rn(c2, c3));
    }
}

// layer 4: 128(half) -> 1, warp per row; out = acc*dinv
__global__ void gemm4_k(const __half* __restrict__ h, const float* __restrict__ W,
                        float* __restrict__ out, int n) {
    int warp = (blockIdx.x * blockDim.x + threadIdx.x) >> 5;
    int lane = threadIdx.x & 31;
    if (warp >= n) return;
    uint2 hv = ((const uint2*)h)[(size_t)warp * 32 + lane];
    float2 h01 = __half22float2(u2h(hv.x));
    float2 h23 = __half22float2(u2h(hv.y));
    float4 wv = __ldg(&((const float4*)W)[lane]);
    float acc = h01.x * wv.x + h01.y * wv.y + h23.x * wv.z + h23.y * wv.w;
#pragma unroll
    for (int off = 16; off; off >>= 1) acc += __shfl_down_sync(0xffffffffu, acc, off);
    if (lane == 0) out[warp] = acc * g_dinv[warp];
}

// ---------------- aggregation (half rows, TPN threads/node, batch-8 MLP) ----------------
template <int TPN, int EPI>
__global__ void agg_h_k(const __half* __restrict__ in_, __half* __restrict__ out_, int n) {
    constexpr int NB = 8 / TPN;
    const uint4* in4 = (const uint4*)in_;
    uint4* out4 = (uint4*)out_;
    int tid = blockIdx.x * 256 + threadIdx.x;
    int node = tid / TPN, f = tid % TPN;
    if (node >= n) return;
    int lane = threadIdx.x & 31;
    int segbase = lane & ~(TPN - 1);
    unsigned mask = ((1u << TPN) - 1u) << segbase;
    float di = g_dinv[node];
    uint4 sv = in4[(size_t)node * TPN + f];
    __half2 a0 = u2h(sv.x), a1 = u2h(sv.y), a2 = u2h(sv.z), a3 = u2h(sv.w);
    __half2 z = __float2half2_rn(0.f);
    __half2 c0 = z, c1 = z, c2 = z, c3 = z;
    int e0 = g_start[node], e1 = e0 + g_indeg[node];
    int e = e0;
    for (; e + 8 <= e1; e += 8) {
        int sl[NB];
#pragma unroll
        for (int j = 0; j < NB; j++) sl[j] = g_csrc[e + j * TPN + f];
        uint4 r[8];
#pragma unroll
        for (int k = 0; k < 8; k++) {
            int sk = __shfl_sync(mask, sl[k / TPN], segbase + (k % TPN), 32);
            r[k] = in4[(size_t)sk * TPN + f];
        }
#pragma unroll
        for (int k = 0; k < 8; k += 2) {
            a0 = __hadd2(a0, u2h(r[k].x));     c0 = __hadd2(c0, u2h(r[k + 1].x));
            a1 = __hadd2(a1, u2h(r[k].y));     c1 = __hadd2(c1, u2h(r[k + 1].y));
            a2 = __hadd2(a2, u2h(r[k].z));     c2 = __hadd2(c2, u2h(r[k + 1].z));
            a3 = __hadd2(a3, u2h(r[k].w));     c3 = __hadd2(c3, u2h(r[k + 1].w));
        }
    }
    for (; e < e1; e++) {
        int s = g_csrc[e];
        uint4 r = in4[(size_t)s * TPN + f];
        a0 = __hadd2(a0, u2h(r.x)); a1 = __hadd2(a1, u2h(r.y));
        a2 = __hadd2(a2, u2h(r.z)); a3 = __hadd2(a3, u2h(r.w));
    }
    float v[8];
    {
        float2 p, q;
        p = __half22float2(a0); q = __half22float2(c0); v[0] = p.x + q.x; v[1] = p.y + q.y;
        p = __half22float2(a1); q = __half22float2(c1); v[2] = p.x + q.x; v[3] = p.y + q.y;
        p = __half22float2(a2); q = __half22float2(c2); v[4] = p.x + q.x; v[5] = p.y + q.y;
        p = __half22float2(a3); q = __half22float2(c3); v[6] = p.x + q.x; v[7] = p.y + q.y;
    }
#pragma unroll
    for (int j = 0; j < 8; j++) v[j] *= di;
    if (EPI == 1) {
        float4 sA = ((const float4*)g_bnS1)[f * 2];
        float4 sB = ((const float4*)g_bnS1)[f * 2 + 1];
        float4 tA = ((const float4*)g_bnT1)[f * 2];
        float4 tB = ((const float4*)g_bnT1)[f * 2 + 1];
        float s[8] = {sA.x, sA.y, sA.z, sA.w, sB.x, sB.y, sB.z, sB.w};
        float t[8] = {tA.x, tA.y, tA.z, tA.w, tB.x, tB.y, tB.z, tB.w};
#pragma unroll
        for (int j = 0; j < 8; j++) {
            float u = v[j] * s[j] + t[j];
            u = (u > 0.f) ? u : expm1f(u);
            v[j] = u * di;
        }
    }
    uint4 o;
    o.x = h2u(__floats2half2_rn(v[0], v[1]));
    o.y = h2u(__floats2half2_rn(v[2], v[3]));
    o.z = h2u(__floats2half2_rn(v[4], v[5]));
    o.w = h2u(__floats2half2_rn(v[6], v[7]));
    out4[(size_t)node * TPN + f] = o;
}

// last layer: scalar rows, batch-4; v = di*(self+sum)+b, ELU, sigmoid
__global__ void agg_last_k(const float* __restrict__ in, const float* __restrict__ b,
                           float* __restrict__ out, int n) {
    int node = blockIdx.x * blockDim.x + threadIdx.x;
    if (node >= n) return;
    float di = g_dinv[node];
    float a0 = in[node], a1 = 0.f, a2 = 0.f, a3 = 0.f;
    int e0 = g_start[node], e1 = e0 + g_indeg[node];
    int e = e0;
    for (; e + 4 <= e1; e += 4) {
        int s0 = g_csrc[e], s1 = g_csrc[e + 1], s2 = g_csrc[e + 2], s3 = g_csrc[e + 3];
        a0 += in[s0]; a1 += in[s1]; a2 += in[s2]; a3 += in[s3];
    }
    for (; e < e1; e++) a0 += in[g_csrc[e]];
    float v = ((a0 + a1) + (a2 + a3)) * di + b[0];
    v = (v > 0.f) ? v : expm1f(v);
    out[node] = 1.f / (1.f + expf(-v));
}

// ---------------- launch ----------------
extern "C" void kernel_launch(void* const* d_in, const int* in_sizes, int n_in,
                              void* d_out, int out_size) {
    const float* x  = (const float*)d_in[0];
    const int*   ei = (const int*)d_in[1];
    const float* W1 = (const float*)d_in[2];  const float* b1 = (const float*)d_in[3];
    const float* W2 = (const float*)d_in[4];  const float* b2 = (const float*)d_in[5];
    const float* W3 = (const float*)d_in[6];  const float* b3 = (const float*)d_in[7];
    const float* W4 = (const float*)d_in[8];  const float* b4 = (const float*)d_in[9];
    const float* g1 = (const float*)d_in[10]; const float* be1 = (const float*)d_in[11];
    const float* rm1 = (const float*)d_in[12]; const float* rv1 = (const float*)d_in[13];
    const float* g2 = (const float*)d_in[14]; const float* be2 = (const float*)d_in[15];
    const float* rm2 = (const float*)d_in[16]; const float* rv2 = (const float*)d_in[17];
    const float* g3 = (const float*)d_in[18]; const float* be3 = (const float*)d_in[19];
    const float* rm3 = (const float*)d_in[20]; const float* rv3 = (const float*)d_in[21];

    int n = in_sizes[0] / 64;       // 100000
    int e = in_sizes[1] / 2;        // 1600000

    __half* hA; cudaGetSymbolAddress((void**)&hA, g_hA);
    __half* hB; cudaGetSymbolAddress((void**)&hB, g_hB);
    __half* hC; cudaGetSymbolAddress((void**)&hC, g_hC);
    float* scal; cudaGetSymbolAddress((void**)&scal, g_scal);
    uint2* w1f; cudaGetSymbolAddress((void**)&w1f, g_w1f);
    uint2* w2f; cudaGetSymbolAddress((void**)&w2f, g_w2f);
    uint2* w3f; cudaGetSymbolAddress((void**)&w3f, g_w3f);
    float* bnS2; cudaGetSymbolAddress((void**)&bnS2, g_bnS2);
    float* bnT2; cudaGetSymbolAddress((void**)&bnT2, g_bnT2);
    float* bnS3; cudaGetSymbolAddress((void**)&bnS3, g_bnS3);
    float* bnT3; cudaGetSymbolAddress((void**)&bnT3, g_bnT3);
    float* out = (float*)d_out;

    int nb_n  = (n + 255) / 256;
    int nb_e4 = (e / 4 + 255) / 256;
    int nb_g  = (n + 127) / 128;

    init_k<<<nb_n, 256>>>(n);
    hist_k<<<nb_e4, 256>>>(ei, e);
    assign_k<<<nb_n, 256>>>(n);
    prep_k<<<13, 256>>>(W1, W2, W3,
                        b1, g1, be1, rm1, rv1,
                        b2, g2, be2, rm2, rv2,
                        b3, g3, be3, rm3, rv3);

    // layer 1 transform: x(f32,64) @ W1 -> *dinv -> hA (half w32)
    gemm_mma_k<64, 32, 0, false><<<nb_g, 256>>>(x, w1f, 0, 0, hA, n);

    scatter_k<<<nb_e4, 256>>>(ei, e);

    // layer 1 agg (+fused BN/ELU, *dinv): hA -> hB (w32)
    agg_h_k<4, 1><<<(n * 4 + 255) / 256, 256>>>(hA, hB, n);

    // layer 2: agg first (w32), then transform 32->64 (+BN/ELU, *dinv)
    agg_h_k<4, 0><<<(n * 4 + 255) / 256, 256>>>(hB, hA, n);
    gemm_mma_k<32, 64, 1, true><<<nb_g, 256>>>(hA, w2f, bnS2, bnT2, hB, n);

    // layer 3: agg first (w64), then transform 64->128 (+BN/ELU) -> half
    agg_h_k<8, 0><<<(n * 8 + 255) / 256, 256>>>(hB, hA, n);
    gemm_mma_k<64, 128, 2, true><<<nb_g, 256>>>(hA, w3f, bnS3, bnT3, hC, n);

    // layer 4: 128->1 (*dinv), agg + ELU + sigmoid
    gemm4_k<<<(n * 32 + 255) / 256, 256>>>(hC, W4, scal, n);
    agg_last_k<<<nb_n, 256>>>(scal, b4, out, n);
}

// round 8
// speedup vs baseline: 4.0965x; 1.0411x over previous
#include <cuda_runtime.h>
#include <cuda_fp16.h>
#include <math.h>

#define MAXN 100096
#define MAXE 1600512
#define EPS 1e-5f

// ---------------- static scratch ----------------
__device__ int    g_indeg[MAXN];
__device__ int    g_cursor[MAXN];
__device__ int    g_start[MAXN];
__device__ int    g_ctr;
__device__ float  g_dinv[MAXN];
__device__ int    g_csrc[MAXE];
__device__ __half g_hA[MAXN * 64];
__device__ __half g_hB[MAXN * 64];
__device__ __half g_hC[MAXN * 128];
__device__ float  g_scal[MAXN];
__device__ float  g_bnS1[32],  g_bnT1[32];
__device__ float  g_bnS2[64],  g_bnT2[64];
__device__ float  g_bnS3[128], g_bnT3[128];
__device__ uint2  g_w1f[4 * 4 * 32];    // NT=4,  KC=4
__device__ uint2  g_w2f[8 * 2 * 32];    // NT=8,  KC=2
__device__ uint2  g_w3f[16 * 4 * 32];   // NT=16, KC=4

// ---------------- half helpers ----------------
__device__ __forceinline__ __half2 u2h(unsigned u) {
    __half2 h; *reinterpret_cast<unsigned*>(&h) = u; return h;
}
__device__ __forceinline__ unsigned h2u(__half2 h) {
    return *reinterpret_cast<unsigned*>(&h);
}

// ---------------- setup ----------------
// weight fragments + BN tables + zero indeg/cursor, one kernel
__device__ __forceinline__ void make_frag(const float* __restrict__ W, int DOUT, int KC,
                                          uint2* __restrict__ dst, int i) {
    int nt = i / (KC * 32);
    int rem = i % (KC * 32);
    int kc = rem / 32, lane = rem % 32;
    int col = nt * 8 + (lane >> 2);
    int kb = kc * 16 + (lane & 3) * 2;
    uint2 o;
    o.x = h2u(__floats2half2_rn(W[kb * DOUT + col],       W[(kb + 1) * DOUT + col]));
    o.y = h2u(__floats2half2_rn(W[(kb + 8) * DOUT + col], W[(kb + 9) * DOUT + col]));
    dst[i] = o;
}
__device__ __forceinline__ void make_bn(const float* b, const float* g, const float* be,
                                        const float* rm, const float* rv,
                                        float* S, float* T, int j) {
    float s = g[j] * rsqrtf(rv[j] + EPS);
    S[j] = s;
    T[j] = (b[j] - rm[j]) * s + be[j];
}
__global__ void prep_k(const float* W1, const float* W2, const float* W3,
                       const float* b1, const float* g1, const float* be1, const float* rm1, const float* rv1,
                       const float* b2, const float* g2, const float* be2, const float* rm2, const float* rv2,
                       const float* b3, const float* g3, const float* be3, const float* rm3, const float* rv3,
                       int n) {
    int i = blockIdx.x * blockDim.x + threadIdx.x;
    if (i < n) { g_indeg[i] = 0; g_cursor[i] = 0; }
    if (i == 0) g_ctr = 0;
    if (i < 512)        make_frag(W1, 32,  4, g_w1f, i);
    else if (i < 1024)  make_frag(W2, 64,  2, g_w2f, i - 512);
    else if (i < 3072)  make_frag(W3, 128, 4, g_w3f, i - 1024);
    else if (i < 3104)  make_bn(b1, g1, be1, rm1, rv1, g_bnS1, g_bnT1, i - 3072);
    else if (i < 3168)  make_bn(b2, g2, be2, rm2, rv2, g_bnS2, g_bnT2, i - 3104);
    else if (i < 3296)  make_bn(b3, g3, be3, rm3, rv3, g_bnS3, g_bnT3, i - 3168);
}

__global__ void hist_k(const int* __restrict__ ei, int e) {
    int i = blockIdx.x * blockDim.x + threadIdx.x;
    const int4* d4 = (const int4*)(ei + e);
    int q = e >> 2;
    if (i < q) {
        int4 d = d4[i];
        atomicAdd(&g_indeg[d.x], 1); atomicAdd(&g_indeg[d.y], 1);
        atomicAdd(&g_indeg[d.z], 1); atomicAdd(&g_indeg[d.w], 1);
    }
    int r = q * 4 + i;
    if (i < (e & 3) && r < e) atomicAdd(&g_indeg[ei[e + r]], 1);
}

// segment-start assignment: warp scan + one atomic per warp (order irrelevant)
__global__ void assign_k(int n) {
    int i = blockIdx.x * blockDim.x + threadIdx.x;
    int lane = threadIdx.x & 31;
    int deg = (i < n) ? g_indeg[i] : 0;
    if (i < n) g_dinv[i] = rsqrtf((float)(deg + 1));
    int run = deg;
#pragma unroll
    for (int off = 1; off < 32; off <<= 1) {
        int t = __shfl_up_sync(0xffffffffu, run, off);
        if (lane >= off) run += t;
    }
    int total = __shfl_sync(0xffffffffu, run, 31);
    int base = 0;
    if (lane == 31) base = atomicAdd(&g_ctr, total);
    base = __shfl_sync(0xffffffffu, base, 31);
    if (i < n) g_start[i] = base + run - deg;
}

__global__ void scatter_k(const int* __restrict__ ei, int e) {
    int i = blockIdx.x * blockDim.x + threadIdx.x;
    const int4* s4 = (const int4*)ei;
    const int4* d4 = (const int4*)(ei + e);
    int q = e >> 2;
    if (i < q) {
        int4 s = s4[i], d = d4[i];
        g_csrc[g_start[d.x] + atomicAdd(&g_cursor[d.x], 1)] = s.x;
        g_csrc[g_start[d.y] + atomicAdd(&g_cursor[d.y], 1)] = s.y;
        g_csrc[g_start[d.z] + atomicAdd(&g_cursor[d.z], 1)] = s.z;
        g_csrc[g_start[d.w] + atomicAdd(&g_cursor[d.w], 1)] = s.w;
    }
    int r = q * 4 + i;
    if (i < (e & 3) && r < e) {
        int s = ei[r], d = ei[e + r];
        g_csrc[g_start[d] + atomicAdd(&g_cursor[d], 1)] = s;
    }
}

// ---------------- tensor-core GEMM: 128 rows/block, mma.m16n8k16 ----------------
// EPI: 0 = acc*dinv (half out)   1 = ELU(BN(acc))*dinv   2 = ELU(BN(acc))
template <int DIN, int DOUT, int EPI, bool IN_HALF>
__global__ void gemm_mma_k(const void* __restrict__ in_, const uint2* __restrict__ wfrag,
                           const float* __restrict__ bnS, const float* __restrict__ bnT,
                           __half* __restrict__ out, int n) {
    constexpr int KC = DIN / 16;
    constexpr int NT = DOUT / 8;
    constexpr int STR = DIN + 4;                 // padded halves per row
    __shared__ __half As[128 * STR];
    __shared__ uint2  Bs[NT * KC * 32];
    int tid = threadIdx.x, wid = tid >> 5, lane = tid & 31;
    int rowbase = blockIdx.x * 128;

    for (int i = tid; i < NT * KC * 32; i += 256) Bs[i] = wfrag[i];

    if (IN_HALF) {
        constexpr int CPR = DIN / 8;             // uint4 per row
        const uint4* src = (const uint4*)in_;
        for (int c = tid; c < 128 * CPR; c += 256) {
            int r = c / CPR, q = c % CPR;
            uint4 v = (rowbase + r < n) ? src[(size_t)(rowbase + r) * CPR + q]
                                        : make_uint4(0, 0, 0, 0);
            __half* p = &As[r * STR + q * 8];
            ((uint2*)p)[0] = make_uint2(v.x, v.y);
            ((uint2*)p)[1] = make_uint2(v.z, v.w);
        }
    } else {
        constexpr int CPR = DIN / 4;             // float4 per row
        const float4* src = (const float4*)in_;
        for (int c = tid; c < 128 * CPR; c += 256) {
            int r = c / CPR, q = c % CPR;
            float4 v = (rowbase + r < n) ? src[(size_t)(rowbase + r) * CPR + q]
                                         : make_float4(0.f, 0.f, 0.f, 0.f);
            uint2 o;
            o.x = h2u(__floats2half2_rn(v.x, v.y));
            o.y = h2u(__floats2half2_rn(v.z, v.w));
            *(uint2*)&As[r * STR + q * 4] = o;
        }
    }
    __syncthreads();

    int g = lane >> 2, t = lane & 3;
    int r0 = wid * 16 + g;
    unsigned a[KC][4];
#pragma unroll
    for (int kc = 0; kc < KC; kc++) {
        int kb = kc * 16 + t * 2;
        a[kc][0] = *(const unsigned*)&As[r0 * STR + kb];
        a[kc][1] = *(const unsigned*)&As[(r0 + 8) * STR + kb];
        a[kc][2] = *(const unsigned*)&As[r0 * STR + kb + 8];
        a[kc][3] = *(const unsigned*)&As[(r0 + 8) * STR + kb + 8];
    }
    int grow0 = rowbase + r0, grow1 = grow0 + 8;
    float di0 = 1.f, di1 = 1.f;
    if (EPI <= 1) {
        di0 = (grow0 < n) ? g_dinv[grow0] : 0.f;
        di1 = (grow1 < n) ? g_dinv[grow1] : 0.f;
    }
#pragma unroll
    for (int nt = 0; nt < NT; nt++) {
        float c0 = 0.f, c1 = 0.f, c2 = 0.f, c3 = 0.f;
#pragma unroll
        for (int kc = 0; kc < KC; kc++) {
            uint2 b = Bs[(nt * KC + kc) * 32 + lane];
            asm volatile(
                "mma.sync.aligned.m16n8k16.row.col.f32.f16.f16.f32 "
                "{%0,%1,%2,%3}, {%4,%5,%6,%7}, {%8,%9}, {%0,%1,%2,%3};\n"
                : "+f"(c0), "+f"(c1), "+f"(c2), "+f"(c3)
                : "r"(a[kc][0]), "r"(a[kc][1]), "r"(a[kc][2]), "r"(a[kc][3]),
                  "r"(b.x), "r"(b.y));
        }
        int col = nt * 8 + t * 2;
        if (EPI >= 1) {
            float s0 = bnS[col], s1 = bnS[col + 1];
            float t0 = bnT[col], t1 = bnT[col + 1];
            c0 = c0 * s0 + t0; c1 = c1 * s1 + t1;
            c2 = c2 * s0 + t0; c3 = c3 * s1 + t1;
            c0 = (c0 > 0.f) ? c0 : expm1f(c0);
            c1 = (c1 > 0.f) ? c1 : expm1f(c1);
            c2 = (c2 > 0.f) ? c2 : expm1f(c2);
            c3 = (c3 > 0.f) ? c3 : expm1f(c3);
        }
        if (EPI <= 1) { c0 *= di0; c1 *= di0; c2 *= di1; c3 *= di1; }
        if (grow0 < n)
            *(unsigned*)&out[(size_t)grow0 * DOUT + col] = h2u(__floats2half2_rn(c0, c1));
        if (grow1 < n)
            *(unsigned*)&out[(size_t)grow1 * DOUT + col] = h2u(__floats2half2_rn(c2, c3));
    }
}

// layer 4: 128(half) -> 1, warp per row; out = acc*dinv
__global__ void gemm4_k(const __half* __restrict__ h, const float* __restrict__ W,
                        float* __restrict__ out, int n) {
    int warp = (blockIdx.x * blockDim.x + threadIdx.x) >> 5;
    int lane = threadIdx.x & 31;
    if (warp >= n) return;
    uint2 hv = ((const uint2*)h)[(size_t)warp * 32 + lane];
    float2 h01 = __half22float2(u2h(hv.x));
    float2 h23 = __half22float2(u2h(hv.y));
    float4 wv = __ldg(&((const float4*)W)[lane]);
    float acc = h01.x * wv.x + h01.y * wv.y + h23.x * wv.z + h23.y * wv.w;
#pragma unroll
    for (int off = 16; off; off >>= 1) acc += __shfl_down_sync(0xffffffffu, acc, off);
    if (lane == 0) out[warp] = acc * g_dinv[warp];
}

// ---------------- aggregation (half rows, TPN threads/node, batch-8 MLP) ----------------
template <int TPN, int EPI>
__global__ void agg_h_k(const __half* __restrict__ in_, __half* __restrict__ out_, int n) {
    constexpr int NB = 8 / TPN;
    const uint4* in4 = (const uint4*)in_;
    uint4* out4 = (uint4*)out_;
    int tid = blockIdx.x * blockDim.x + threadIdx.x;
    int node = tid / TPN, f = tid % TPN;
    if (node >= n) return;
    int lane = threadIdx.x & 31;
    int segbase = lane & ~(TPN - 1);
    unsigned mask = ((1u << TPN) - 1u) << segbase;
    float di = g_dinv[node];
    uint4 sv = in4[(size_t)node * TPN + f];
    __half2 a0 = u2h(sv.x), a1 = u2h(sv.y), a2 = u2h(sv.z), a3 = u2h(sv.w);
    __half2 z = __float2half2_rn(0.f);
    __half2 c0 = z, c1 = z, c2 = z, c3 = z;
    int e0 = g_start[node], e1 = e0 + g_indeg[node];
    int e = e0;
    for (; e + 8 <= e1; e += 8) {
        int sl[NB];
#pragma unroll
        for (int j = 0; j < NB; j++) sl[j] = __ldg(&g_csrc[e + j * TPN + f]);
        uint4 r[8];
#pragma unroll
        for (int k = 0; k < 8; k++) {
            int sk = __shfl_sync(mask, sl[k / TPN], segbase + (k % TPN), 32);
            r[k] = in4[(size_t)sk * TPN + f];
        }
#pragma unroll
        for (int k = 0; k < 8; k += 2) {
            a0 = __hadd2(a0, u2h(r[k].x));     c0 = __hadd2(c0, u2h(r[k + 1].x));
            a1 = __hadd2(a1, u2h(r[k].y));     c1 = __hadd2(c1, u2h(r[k + 1].y));
            a2 = __hadd2(a2, u2h(r[k].z));     c2 = __hadd2(c2, u2h(r[k + 1].z));
            a3 = __hadd2(a3, u2h(r[k].w));     c3 = __hadd2(c3, u2h(r[k + 1].w));
        }
    }
    for (; e < e1; e++) {
        int s = __ldg(&g_csrc[e]);
        uint4 r = in4[(size_t)s * TPN + f];
        a0 = __hadd2(a0, u2h(r.x)); a1 = __hadd2(a1, u2h(r.y));
        a2 = __hadd2(a2, u2h(r.z)); a3 = __hadd2(a3, u2h(r.w));
    }
    float v[8];
    {
        float2 p, q;
        p = __half22float2(a0); q = __half22float2(c0); v[0] = p.x + q.x; v[1] = p.y + q.y;
        p = __half22float2(a1); q = __half22float2(c1); v[2] = p.x + q.x; v[3] = p.y + q.y;
        p = __half22float2(a2); q = __half22float2(c2); v[4] = p.x + q.x; v[5] = p.y + q.y;
        p = __half22float2(a3); q = __half22float2(c3); v[6] = p.x + q.x; v[7] = p.y + q.y;
    }
#pragma unroll
    for (int j = 0; j < 8; j++) v[j] *= di;
    if (EPI == 1) {
        float4 sA = ((const float4*)g_bnS1)[f * 2];
        float4 sB = ((const float4*)g_bnS1)[f * 2 + 1];
        float4 tA = ((const float4*)g_bnT1)[f * 2];
        float4 tB = ((const float4*)g_bnT1)[f * 2 + 1];
        float s[8] = {sA.x, sA.y, sA.z, sA.w, sB.x, sB.y, sB.z, sB.w};
        float t[8] = {tA.x, tA.y, tA.z, tA.w, tB.x, tB.y, tB.z, tB.w};
#pragma unroll
        for (int j = 0; j < 8; j++) {
            float u = v[j] * s[j] + t[j];
            u = (u > 0.f) ? u : expm1f(u);
            v[j] = u * di;
        }
    }
    uint4 o;
    o.x = h2u(__floats2half2_rn(v[0], v[1]));
    o.y = h2u(__floats2half2_rn(v[2], v[3]));
    o.z = h2u(__floats2half2_rn(v[4], v[5]));
    o.w = h2u(__floats2half2_rn(v[6], v[7]));
    out4[(size_t)node * TPN + f] = o;
}

// last layer: scalar rows, batch-4; v = di*(self+sum)+b, ELU, sigmoid
__global__ void agg_last_k(const float* __restrict__ in, const float* __restrict__ b,
                           float* __restrict__ out, int n) {
    int node = blockIdx.x * blockDim.x + threadIdx.x;
    if (node >= n) return;
    float di = g_dinv[node];
    float a0 = in[node], a1 = 0.f, a2 = 0.f, a3 = 0.f;
    int e0 = g_start[node], e1 = e0 + g_indeg[node];
    int e = e0;
    for (; e + 4 <= e1; e += 4) {
        int s0 = __ldg(&g_csrc[e]),     s1 = __ldg(&g_csrc[e + 1]);
        int s2 = __ldg(&g_csrc[e + 2]), s3 = __ldg(&g_csrc[e + 3]);
        a0 += in[s0]; a1 += in[s1]; a2 += in[s2]; a3 += in[s3];
    }
    for (; e < e1; e++) a0 += in[__ldg(&g_csrc[e])];
    float v = ((a0 + a1) + (a2 + a3)) * di + b[0];
    v = (v > 0.f) ? v : expm1f(v);
    out[node] = 1.f / (1.f + expf(-v));
}

// ---------------- launch ----------------
extern "C" void kernel_launch(void* const* d_in, const int* in_sizes, int n_in,
                              void* d_out, int out_size) {
    const float* x  = (const float*)d_in[0];
    const int*   ei = (const int*)d_in[1];
    const float* W1 = (const float*)d_in[2];  const float* b1 = (const float*)d_in[3];
    const float* W2 = (const float*)d_in[4];  const float* b2 = (const float*)d_in[5];
    const float* W3 = (const float*)d_in[6];  const float* b3 = (const float*)d_in[7];
    const float* W4 = (const float*)d_in[8];  const float* b4 = (const float*)d_in[9];
    const float* g1 = (const float*)d_in[10]; const float* be1 = (const float*)d_in[11];
    const float* rm1 = (const float*)d_in[12]; const float* rv1 = (const float*)d_in[13];
    const float* g2 = (const float*)d_in[14]; const float* be2 = (const float*)d_in[15];
    const float* rm2 = (const float*)d_in[16]; const float* rv2 = (const float*)d_in[17];
    const float* g3 = (const float*)d_in[18]; const float* be3 = (const float*)d_in[19];
    const float* rm3 = (const float*)d_in[20]; const float* rv3 = (const float*)d_in[21];

    int n = in_sizes[0] / 64;       // 100000
    int e = in_sizes[1] / 2;        // 1600000

    __half* hA; cudaGetSymbolAddress((void**)&hA, g_hA);
    __half* hB; cudaGetSymbolAddress((void**)&hB, g_hB);
    __half* hC; cudaGetSymbolAddress((void**)&hC, g_hC);
    float* scal; cudaGetSymbolAddress((void**)&scal, g_scal);
    uint2* w1f; cudaGetSymbolAddress((void**)&w1f, g_w1f);
    uint2* w2f; cudaGetSymbolAddress((void**)&w2f, g_w2f);
    uint2* w3f; cudaGetSymbolAddress((void**)&w3f, g_w3f);
    float* bnS2; cudaGetSymbolAddress((void**)&bnS2, g_bnS2);
    float* bnT2; cudaGetSymbolAddress((void**)&bnT2, g_bnT2);
    float* bnS3; cudaGetSymbolAddress((void**)&bnS3, g_bnS3);
    float* bnT3; cudaGetSymbolAddress((void**)&bnT3, g_bnT3);
    float* out = (float*)d_out;

    int nb_n  = (n + 255) / 256;
    int nb_e4 = (e / 4 + 255) / 256;
    int nb_g  = (n + 127) / 128;

    // side stream + events for fork-join overlap (created per call; kernel_launch
    // is invoked only a handful of times, never during replay)
    cudaStream_t s2;
    cudaStreamCreateWithFlags(&s2, cudaStreamNonBlocking);
    cudaEvent_t evP, evG;
    cudaEventCreateWithFlags(&evP, cudaEventDisableTiming);
    cudaEventCreateWithFlags(&evG, cudaEventDisableTiming);

    // (0) prep: init counters + weight frags + BN tables
    prep_k<<<nb_n, 256>>>(W1, W2, W3,
                          b1, g1, be1, rm1, rv1,
                          b2, g2, be2, rm2, rv2,
                          b3, g3, be3, rm3, rv3, n);
    cudaEventRecord(evP, 0);

    // (1) gemm1 on side stream, overlapped with edge-CSR chain
    cudaStreamWaitEvent(s2, evP, 0);
    gemm_mma_k<64, 32, 0, false><<<nb_g, 256, 0, s2>>>(x, w1f, 0, 0, hA, n);
    cudaEventRecord(evG, s2);

    // (2,3,4) edge chain on main stream
    hist_k<<<nb_e4, 256>>>(ei, e);
    assign_k<<<nb_n, 256>>>(n);
    scatter_k<<<nb_e4, 256>>>(ei, e);

    // join
    cudaStreamWaitEvent(0, evG, 0);

    // (5) layer 1 agg (+fused BN/ELU, *dinv): hA -> hB (w32)   <-- ncu -s 5 target
    agg_h_k<4, 1><<<(n * 4 + 255) / 256, 256>>>(hA, hB, n);

    // layer 2: agg first (w32), then transform 32->64 (+BN/ELU, *dinv)
    agg_h_k<4, 0><<<(n * 4 + 255) / 256, 256>>>(hB, hA, n);
    gemm_mma_k<32, 64, 1, true><<<nb_g, 256>>>(hA, w2f, bnS2, bnT2, hB, n);

    // layer 3: agg first (w64), then transform 64->128 (+BN/ELU) -> half
    agg_h_k<8, 0><<<(n * 8 + 255) / 256, 256>>>(hB, hA, n);
    gemm_mma_k<64, 128, 2, true><<<nb_g, 256>>>(hA, w3f, bnS3, bnT3, hC, n);

    // layer 4: 128->1 (*dinv), agg + ELU + sigmoid
    gemm4_k<<<(n * 32 + 255) / 256, 256>>>(hC, W4, scal, n);
    agg_last_k<<<nb_n, 256>>>(scal, b4, out, n);
}

// round 9
// speedup vs baseline: 4.4793x; 1.0934x over previous
#include <cuda_runtime.h>
#include <cuda_fp16.h>
#include <math.h>

#define MAXN 100096
#define MAXE 1600512
#define EPS 1e-5f

// ---------------- static scratch ----------------
__device__ int    g_indeg[MAXN];
__device__ int    g_cursor[MAXN];
__device__ int    g_start[MAXN];
__device__ int    g_ctr;
__device__ float  g_dinv[MAXN];
__device__ int    g_csrc[MAXE];
__device__ __half g_hA[MAXN * 64];
__device__ __half g_hB[MAXN * 64];
__device__ float  g_scal[MAXN];
__device__ float  g_bnS1[32],  g_bnT1[32];
__device__ float  g_bnS2[64],  g_bnT2[64];
__device__ float  g_bnS3[128], g_bnT3[128];
__device__ uint2  g_w1f[4 * 4 * 32];    // NT=4,  KC=4
__device__ uint2  g_w2f[8 * 2 * 32];    // NT=8,  KC=2
__device__ uint2  g_w3f[16 * 4 * 32];   // NT=16, KC=4

// ---------------- half helpers ----------------
__device__ __forceinline__ __half2 u2h(unsigned u) {
    __half2 h; *reinterpret_cast<unsigned*>(&h) = u; return h;
}
__device__ __forceinline__ unsigned h2u(__half2 h) {
    return *reinterpret_cast<unsigned*>(&h);
}

// ---------------- setup ----------------
__device__ __forceinline__ void make_frag(const float* __restrict__ W, int DOUT, int KC,
                                          uint2* __restrict__ dst, int i) {
    int nt = i / (KC * 32);
    int rem = i % (KC * 32);
    int kc = rem / 32, lane = rem % 32;
    int col = nt * 8 + (lane >> 2);
    int kb = kc * 16 + (lane & 3) * 2;
    uint2 o;
    o.x = h2u(__floats2half2_rn(W[kb * DOUT + col],       W[(kb + 1) * DOUT + col]));
    o.y = h2u(__floats2half2_rn(W[(kb + 8) * DOUT + col], W[(kb + 9) * DOUT + col]));
    dst[i] = o;
}
__device__ __forceinline__ void make_bn(const float* b, const float* g, const float* be,
                                        const float* rm, const float* rv,
                                        float* S, float* T, int j) {
    float s = g[j] * rsqrtf(rv[j] + EPS);
    S[j] = s;
    T[j] = (b[j] - rm[j]) * s + be[j];
}
__global__ void prep_k(const float* W1, const float* W2, const float* W3,
                       const float* b1, const float* g1, const float* be1, const float* rm1, const float* rv1,
                       const float* b2, const float* g2, const float* be2, const float* rm2, const float* rv2,
                       const float* b3, const float* g3, const float* be3, const float* rm3, const float* rv3,
                       int n) {
    int i = blockIdx.x * blockDim.x + threadIdx.x;
    if (i < n) { g_indeg[i] = 0; g_cursor[i] = 0; }
    if (i == 0) g_ctr = 0;
    if (i < 512)        make_frag(W1, 32,  4, g_w1f, i);
    else if (i < 1024)  make_frag(W2, 64,  2, g_w2f, i - 512);
    else if (i < 3072)  make_frag(W3, 128, 4, g_w3f, i - 1024);
    else if (i < 3104)  make_bn(b1, g1, be1, rm1, rv1, g_bnS1, g_bnT1, i - 3072);
    else if (i < 3168)  make_bn(b2, g2, be2, rm2, rv2, g_bnS2, g_bnT2, i - 3104);
    else if (i < 3296)  make_bn(b3, g3, be3, rm3, rv3, g_bnS3, g_bnT3, i - 3168);
}

__global__ void hist_k(const int* __restrict__ ei, int e) {
    int i = blockIdx.x * blockDim.x + threadIdx.x;
    const int4* d4 = (const int4*)(ei + e);
    int q = e >> 2;
    if (i < q) {
        int4 d = d4[i];
        atomicAdd(&g_indeg[d.x], 1); atomicAdd(&g_indeg[d.y], 1);
        atomicAdd(&g_indeg[d.z], 1); atomicAdd(&g_indeg[d.w], 1);
    }
    int r = q * 4 + i;
    if (i < (e & 3) && r < e) atomicAdd(&g_indeg[ei[e + r]], 1);
}

__global__ void assign_k(int n) {
    int i = blockIdx.x * blockDim.x + threadIdx.x;
    int lane = threadIdx.x & 31;
    int deg = (i < n) ? g_indeg[i] : 0;
    if (i < n) g_dinv[i] = rsqrtf((float)(deg + 1));
    int run = deg;
#pragma unroll
    for (int off = 1; off < 32; off <<= 1) {
        int t = __shfl_up_sync(0xffffffffu, run, off);
        if (lane >= off) run += t;
    }
    int total = __shfl_sync(0xffffffffu, run, 31);
    int base = 0;
    if (lane == 31) base = atomicAdd(&g_ctr, total);
    base = __shfl_sync(0xffffffffu, base, 31);
    if (i < n) g_start[i] = base + run - deg;
}

__global__ void scatter_k(const int* __restrict__ ei, int e) {
    int i = blockIdx.x * blockDim.x + threadIdx.x;
    const int4* s4 = (const int4*)ei;
    const int4* d4 = (const int4*)(ei + e);
    int q = e >> 2;
    if (i < q) {
        int4 s = s4[i], d = d4[i];
        g_csrc[g_start[d.x] + atomicAdd(&g_cursor[d.x], 1)] = s.x;
        g_csrc[g_start[d.y] + atomicAdd(&g_cursor[d.y], 1)] = s.y;
        g_csrc[g_start[d.z] + atomicAdd(&g_cursor[d.z], 1)] = s.z;
        g_csrc[g_start[d.w] + atomicAdd(&g_cursor[d.w], 1)] = s.w;
    }
    int r = q * 4 + i;
    if (i < (e & 3) && r < e) {
        int s = ei[r], d = ei[e + r];
        g_csrc[g_start[d] + atomicAdd(&g_cursor[d], 1)] = s;
    }
}

// ---------------- tensor-core GEMM: 128 rows/block, mma.m16n8k16 ----------------
// EPI: 0 = acc*dinv (half out)   1 = ELU(BN(acc))*dinv (half out)
//      3 = fused L3+L4: scal[row] = (ELU(BN(acc)) . W4) * dinv (float out)
template <int DIN, int DOUT, int EPI, bool IN_HALF>
__global__ void gemm_mma_k(const void* __restrict__ in_, const uint2* __restrict__ wfrag,
                           const float* __restrict__ bnS, const float* __restrict__ bnT,
                           const float* __restrict__ W4, void* __restrict__ out_, int n) {
    constexpr int KC = DIN / 16;
    constexpr int NT = DOUT / 8;
    constexpr int STR = DIN + 4;                 // padded halves per row
    __shared__ __half As[128 * STR];
    __shared__ uint2  Bs[NT * KC * 32];
    int tid = threadIdx.x, wid = tid >> 5, lane = tid & 31;
    int rowbase = blockIdx.x * 128;

    for (int i = tid; i < NT * KC * 32; i += 256) Bs[i] = wfrag[i];

    if (IN_HALF) {
        constexpr int CPR = DIN / 8;             // uint4 per row
        const uint4* src = (const uint4*)in_;
        for (int c = tid; c < 128 * CPR; c += 256) {
            int r = c / CPR, q = c % CPR;
            uint4 v = (rowbase + r < n) ? src[(size_t)(rowbase + r) * CPR + q]
                                        : make_uint4(0, 0, 0, 0);
            __half* p = &As[r * STR + q * 8];
            ((uint2*)p)[0] = make_uint2(v.x, v.y);
            ((uint2*)p)[1] = make_uint2(v.z, v.w);
        }
    } else {
        constexpr int CPR = DIN / 4;             // float4 per row
        const float4* src = (const float4*)in_;
        for (int c = tid; c < 128 * CPR; c += 256) {
            int r = c / CPR, q = c % CPR;
            float4 v = (rowbase + r < n) ? src[(size_t)(rowbase + r) * CPR + q]
                                         : make_float4(0.f, 0.f, 0.f, 0.f);
            uint2 o;
            o.x = h2u(__floats2half2_rn(v.x, v.y));
            o.y = h2u(__floats2half2_rn(v.z, v.w));
            *(uint2*)&As[r * STR + q * 4] = o;
        }
    }
    __syncthreads();

    int g = lane >> 2, t = lane & 3;
    int r0 = wid * 16 + g;
    unsigned a[KC][4];
#pragma unroll
    for (int kc = 0; kc < KC; kc++) {
        int kb = kc * 16 + t * 2;
        a[kc][0] = *(const unsigned*)&As[r0 * STR + kb];
        a[kc][1] = *(const unsigned*)&As[(r0 + 8) * STR + kb];
        a[kc][2] = *(const unsigned*)&As[r0 * STR + kb + 8];
        a[kc][3] = *(const unsigned*)&As[(r0 + 8) * STR + kb + 8];
    }
    int grow0 = rowbase + r0, grow1 = grow0 + 8;
    float di0 = (grow0 < n) ? g_dinv[grow0] : 0.f;
    float di1 = (grow1 < n) ? g_dinv[grow1] : 0.f;
    float accR0 = 0.f, accR1 = 0.f;              // EPI==3 row partials
#pragma unroll
    for (int nt = 0; nt < NT; nt++) {
        float c0 = 0.f, c1 = 0.f, c2 = 0.f, c3 = 0.f;
#pragma unroll
        for (int kc = 0; kc < KC; kc++) {
            uint2 b = Bs[(nt * KC + kc) * 32 + lane];
            asm volatile(
                "mma.sync.aligned.m16n8k16.row.col.f32.f16.f16.f32 "
                "{%0,%1,%2,%3}, {%4,%5,%6,%7}, {%8,%9}, {%0,%1,%2,%3};\n"
                : "+f"(c0), "+f"(c1), "+f"(c2), "+f"(c3)
                : "r"(a[kc][0]), "r"(a[kc][1]), "r"(a[kc][2]), "r"(a[kc][3]),
                  "r"(b.x), "r"(b.y));
        }
        int col = nt * 8 + t * 2;
        if (EPI >= 1) {
            float s0 = bnS[col], s1 = bnS[col + 1];
            float t0 = bnT[col], t1 = bnT[col + 1];
            c0 = c0 * s0 + t0; c1 = c1 * s1 + t1;
            c2 = c2 * s0 + t0; c3 = c3 * s1 + t1;
            c0 = (c0 > 0.f) ? c0 : expm1f(c0);
            c1 = (c1 > 0.f) ? c1 : expm1f(c1);
            c2 = (c2 > 0.f) ? c2 : expm1f(c2);
            c3 = (c3 > 0.f) ? c3 : expm1f(c3);
        }
        if (EPI == 3) {
            float w0 = __ldg(&W4[col]), w1 = __ldg(&W4[col + 1]);
            accR0 += c0 * w0 + c1 * w1;
            accR1 += c2 * w0 + c3 * w1;
        } else {
            c0 *= di0; c1 *= di0; c2 *= di1; c3 *= di1;
            __half* out = (__half*)out_;
            if (grow0 < n)
                *(unsigned*)&out[(size_t)grow0 * DOUT + col] = h2u(__floats2half2_rn(c0, c1));
            if (grow1 < n)
                *(unsigned*)&out[(size_t)grow1 * DOUT + col] = h2u(__floats2half2_rn(c2, c3));
        }
    }
    if (EPI == 3) {
        // reduce across the 4 lanes of the quad (disjoint column pairs)
        accR0 += __shfl_xor_sync(0xffffffffu, accR0, 1);
        accR0 += __shfl_xor_sync(0xffffffffu, accR0, 2);
        accR1 += __shfl_xor_sync(0xffffffffu, accR1, 1);
        accR1 += __shfl_xor_sync(0xffffffffu, accR1, 2);
        float* scal = (float*)out_;
        if (t == 0) {
            if (grow0 < n) scal[grow0] = accR0 * di0;
            if (grow1 < n) scal[grow1] = accR1 * di1;
        }
    }
}

// ---------------- aggregation (half rows, f32 accumulators, batch-8 MLP) ----------------
// ac += 2*(r0+r1): one HADD2 in half per pair, then FFMA-imm(2.0) into f32; halved at end.
template <int TPN, int EPI>
__global__ void agg_h_k(const __half* __restrict__ in_, __half* __restrict__ out_, int n) {
    constexpr int NB = 8 / TPN;
    const uint4* in4 = (const uint4*)in_;
    uint4* out4 = (uint4*)out_;
    int tid = blockIdx.x * blockDim.x + threadIdx.x;
    int node = tid / TPN, f = tid % TPN;
    if (node >= n) return;
    int lane = threadIdx.x & 31;
    int segbase = lane & ~(TPN - 1);
    unsigned mask = ((1u << TPN) - 1u) << segbase;
    float di = g_dinv[node];
    float se[8], ac[8];
    {
        uint4 sv = in4[(size_t)node * TPN + f];
        float2 p;
        p = __half22float2(u2h(sv.x)); se[0] = p.x; se[1] = p.y;
        p = __half22float2(u2h(sv.y)); se[2] = p.x; se[3] = p.y;
        p = __half22float2(u2h(sv.z)); se[4] = p.x; se[5] = p.y;
        p = __half22float2(u2h(sv.w)); se[6] = p.x; se[7] = p.y;
    }
#pragma unroll
    for (int j = 0; j < 8; j++) ac[j] = 0.f;
    int e0 = g_start[node], e1 = e0 + g_indeg[node];
    int e = e0;
    for (; e + 8 <= e1; e += 8) {
        int sl[NB];
#pragma unroll
        for (int j = 0; j < NB; j++) sl[j] = __ldg(&g_csrc[e + j * TPN + f]);
        uint4 r[8];
#pragma unroll
        for (int k = 0; k < 8; k++) {
            int sk = __shfl_sync(mask, sl[k / TPN], segbase + (k % TPN), 32);
            r[k] = in4[(size_t)sk * TPN + f];
        }
#pragma unroll
        for (int k = 0; k < 8; k += 2) {
            __half2 p0 = __hadd2(u2h(r[k].x), u2h(r[k + 1].x));
            __half2 p1 = __hadd2(u2h(r[k].y), u2h(r[k + 1].y));
            __half2 p2 = __hadd2(u2h(r[k].z), u2h(r[k + 1].z));
            __half2 p3 = __hadd2(u2h(r[k].w), u2h(r[k + 1].w));
            float2 f0 = __half22float2(p0);
            float2 f1 = __half22float2(p1);
            float2 f2 = __half22float2(p2);
            float2 f3 = __half22float2(p3);
            ac[0] = fmaf(f0.x, 2.0f, ac[0]); ac[1] = fmaf(f0.y, 2.0f, ac[1]);
            ac[2] = fmaf(f1.x, 2.0f, ac[2]); ac[3] = fmaf(f1.y, 2.0f, ac[3]);
            ac[4] = fmaf(f2.x, 2.0f, ac[4]); ac[5] = fmaf(f2.y, 2.0f, ac[5]);
            ac[6] = fmaf(f3.x, 2.0f, ac[6]); ac[7] = fmaf(f3.y, 2.0f, ac[7]);
        }
    }
    for (; e < e1; e++) {
        int s = __ldg(&g_csrc[e]);
        uint4 r = in4[(size_t)s * TPN + f];
        float2 p;
        p = __half22float2(u2h(r.x)); se[0] += p.x; se[1] += p.y;
        p = __half22float2(u2h(r.y)); se[2] += p.x; se[3] += p.y;
        p = __half22float2(u2h(r.z)); se[4] += p.x; se[5] += p.y;
        p = __half22float2(u2h(r.w)); se[6] += p.x; se[7] += p.y;
    }
    float v[8];
#pragma unroll
    for (int j = 0; j < 8; j++) v[j] = fmaf(ac[j], 0.5f, se[j]) * di;
    if (EPI == 1) {
        float4 sA = ((const float4*)g_bnS1)[f * 2];
        float4 sB = ((const float4*)g_bnS1)[f * 2 + 1];
        float4 tA = ((const float4*)g_bnT1)[f * 2];
        float4 tB = ((const float4*)g_bnT1)[f * 2 + 1];
        float s[8] = {sA.x, sA.y, sA.z, sA.w, sB.x, sB.y, sB.z, sB.w};
        float t[8] = {tA.x, tA.y, tA.z, tA.w, tB.x, tB.y, tB.z, tB.w};
#pragma unroll
        for (int j = 0; j < 8; j++) {
            float u = v[j] * s[j] + t[j];
            u = (u > 0.f) ? u : expm1f(u);
            v[j] = u * di;
        }
    }
    uint4 o;
    o.x = h2u(__floats2half2_rn(v[0], v[1]));
    o.y = h2u(__floats2half2_rn(v[2], v[3]));
    o.z = h2u(__floats2half2_rn(v[4], v[5]));
    o.w = h2u(__floats2half2_rn(v[6], v[7]));
    out4[(size_t)node * TPN + f] = o;
}

// last layer: scalar rows, batch-4; v = di*(self+sum)+b, ELU, sigmoid
__global__ void agg_last_k(const float* __restrict__ in, const float* __restrict__ b,
                           float* __restrict__ out, int n) {
    int node = blockIdx.x * blockDim.x + threadIdx.x;
    if (node >= n) return;
    float di = g_dinv[node];
    float a0 = in[node], a1 = 0.f, a2 = 0.f, a3 = 0.f;
    int e0 = g_start[node], e1 = e0 + g_indeg[node];
    int e = e0;
    for (; e + 4 <= e1; e += 4) {
        int s0 = __ldg(&g_csrc[e]),     s1 = __ldg(&g_csrc[e + 1]);
        int s2 = __ldg(&g_csrc[e + 2]), s3 = __ldg(&g_csrc[e + 3]);
        a0 += in[s0]; a1 += in[s1]; a2 += in[s2]; a3 += in[s3];
    }
    for (; e < e1; e++) a0 += in[__ldg(&g_csrc[e])];
    float v = ((a0 + a1) + (a2 + a3)) * di + b[0];
    v = (v > 0.f) ? v : expm1f(v);
    out[node] = 1.f / (1.f + expf(-v));
}

// ---------------- launch ----------------
extern "C" void kernel_launch(void* const* d_in, const int* in_sizes, int n_in,
                              void* d_out, int out_size) {
    const float* x  = (const float*)d_in[0];
    const int*   ei = (const int*)d_in[1];
    const float* W1 = (const float*)d_in[2];  const float* b1 = (const float*)d_in[3];
    const float* W2 = (const float*)d_in[4];  const float* b2 = (const float*)d_in[5];
    const float* W3 = (const float*)d_in[6];  const float* b3 = (const float*)d_in[7];
    const float* W4 = (const float*)d_in[8];  const float* b4 = (const float*)d_in[9];
    const float* g1 = (const float*)d_in[10]; const float* be1 = (const float*)d_in[11];
    const float* rm1 = (const float*)d_in[12]; const float* rv1 = (const float*)d_in[13];
    const float* g2 = (const float*)d_in[14]; const float* be2 = (const float*)d_in[15];
    const float* rm2 = (const float*)d_in[16]; const float* rv2 = (const float*)d_in[17];
    const float* g3 = (const float*)d_in[18]; const float* be3 = (const float*)d_in[19];
    const float* rm3 = (const float*)d_in[20]; const float* rv3 = (const float*)d_in[21];

    int n = in_sizes[0] / 64;       // 100000
    int e = in_sizes[1] / 2;        // 1600000

    __half* hA; cudaGetSymbolAddress((void**)&hA, g_hA);
    __half* hB; cudaGetSymbolAddress((void**)&hB, g_hB);
    float* scal; cudaGetSymbolAddress((void**)&scal, g_scal);
    uint2* w1f; cudaGetSymbolAddress((void**)&w1f, g_w1f);
    uint2* w2f; cudaGetSymbolAddress((void**)&w2f, g_w2f);
    uint2* w3f; cudaGetSymbolAddress((void**)&w3f, g_w3f);
    float* bnS2; cudaGetSymbolAddress((void**)&bnS2, g_bnS2);
    float* bnT2; cudaGetSymbolAddress((void**)&bnT2, g_bnT2);
    float* bnS3; cudaGetSymbolAddress((void**)&bnS3, g_bnS3);
    float* bnT3; cudaGetSymbolAddress((void**)&bnT3, g_bnT3);
    float* out = (float*)d_out;

    int nb_n  = (n + 255) / 256;
    int nb_e4 = (e / 4 + 255) / 256;
    int nb_g  = (n + 127) / 128;

    cudaStream_t s2;
    cudaStreamCreateWithFlags(&s2, cudaStreamNonBlocking);
    cudaEvent_t evP, evG;
    cudaEventCreateWithFlags(&evP, cudaEventDisableTiming);
    cudaEventCreateWithFlags(&evG, cudaEventDisableTiming);

    // (0) prep: init counters + weight frags + BN tables
    prep_k<<<nb_n, 256>>>(W1, W2, W3,
                          b1, g1, be1, rm1, rv1,
                          b2, g2, be2, rm2, rv2,
                          b3, g3, be3, rm3, rv3, n);
    cudaEventRecord(evP, 0);

    // gemm1 on side stream, overlapped with edge-CSR chain
    cudaStreamWaitEvent(s2, evP, 0);
    gemm_mma_k<64, 32, 0, false><<<nb_g, 256, 0, s2>>>(x, w1f, 0, 0, 0, hA, n);
    cudaEventRecord(evG, s2);

    // edge chain on main stream
    hist_k<<<nb_e4, 256>>>(ei, e);
    assign_k<<<nb_n, 256>>>(n);
    scatter_k<<<nb_e4, 256>>>(ei, e);

    // join
    cudaStreamWaitEvent(0, evG, 0);

    // layer 1 agg (+fused BN/ELU, *dinv): hA -> hB (w32)
    agg_h_k<4, 1><<<(n * 4 + 255) / 256, 256>>>(hA, hB, n);

    // layer 2: agg first (w32), then transform 32->64 (+BN/ELU, *dinv)
    agg_h_k<4, 0><<<(n * 4 + 255) / 256, 256>>>(hB, hA, n);
    gemm_mma_k<32, 64, 1, true><<<nb_g, 256>>>(hA, w2f, bnS2, bnT2, 0, hB, n);

    // layer 3+4 fused: agg (w64), then 64->128 (+BN/ELU) . W4 -> scal (*dinv)
    agg_h_k<8, 0><<<(n * 8 + 255) / 256, 256>>>(hB, hA, n);
    gemm_mma_k<64, 128, 3, true><<<nb_g, 256>>>(hA, w3f, bnS3, bnT3, W4, scal, n);

    // final agg + bias + ELU + sigmoid
    agg_last_k<<<nb_n, 256>>>(scal, b4, out, n);
}